// round 1
// baseline (speedup 1.0000x reference)
#include <cuda_runtime.h>
#include <cuda_bf16.h>
#include <math.h>

// ---------------- problem constants ----------------
#define BB    2
#define C1    64
#define C2    256
#define C3    256
#define HH    200
#define WW2   200
#define HW    40000        // HH*WW2
#define NPIX  80000        // BB*HW
#define HEADS 8
#define HD    32           // C3/HEADS
#define WS    7
#define PADW  3
#define CF    1024         // 4*C3
#define SCALE 0.17677669529663689f   // HD^-0.5
#define LNEPS 1e-5f

// ---------------- scratch (device globals; no runtime allocation) ----------------
__device__ float g_Q [(long)BB*C3*HW];
__device__ float g_K [(long)BB*C3*HW];
__device__ float g_V [(long)BB*C3*HW];
__device__ float g_AO[(long)BB*C3*HW];
__device__ float g_T1[(long)BB*C3*HW];
__device__ float g_X [(long)NPIX*C3];
__device__ float g_Y [(long)NPIX*CF];
__device__ float g_Z [(long)NPIX*C3];

// ---------------- generic SGEMM ----------------
// C[M,N] = A[M,K] (row-major, lda) * B[K,N] (row-major, ldb)  [+ C] [+ bias[col]] [+ Res] [relu]
// Batched over gridDim.z with byte-element strides strideB/strideC (A shared unless strideA used=0).
// Assumes K % BK == 0 and N % 4 == 0 (true for all call sites here).
#define BM 128
#define BN 128
#define TM 8
#define TN 8

template<int BK, bool ACCUM, bool BIAS, bool RELU, bool RESID>
__global__ __launch_bounds__(256)
void sgemm_kernel(const float* __restrict__ A, const float* __restrict__ B,
                  float* __restrict__ C, const float* __restrict__ bias,
                  const float* __restrict__ Res,
                  int M, int N, int K, int lda, int ldb, int ldc,
                  long strideB, long strideC)
{
    B += (long)blockIdx.z * strideB;
    C += (long)blockIdx.z * strideC;
    const float* ResB = RESID ? (Res + (long)blockIdx.z * strideC) : nullptr;

    __shared__ float As[BK][BM];
    __shared__ float Bs[BK][BN];

    const int tid = threadIdx.x;
    const int tr  = tid / (BN / TN);   // 0..15
    const int tc  = tid % (BN / TN);   // 0..15

    const int rowBase = blockIdx.y * BM;
    const int colBase = blockIdx.x * BN;

    const int aRow  = tid / (BK / 4);          // BK=16 -> 0..63
    const int aCol4 = (tid % (BK / 4)) * 4;
    const int bRow  = tid / (BN / 4);          // 0..7
    const int bCol4 = (tid % (BN / 4)) * 4;

    float acc[TM][TN];
    #pragma unroll
    for (int i = 0; i < TM; i++)
        #pragma unroll
        for (int j = 0; j < TN; j++) acc[i][j] = 0.f;

    for (int k0 = 0; k0 < K; k0 += BK) {
        // load A tile (BM x BK), store transposed
        #pragma unroll
        for (int i = 0; i < BM; i += 256 / (BK / 4)) {
            int r = rowBase + aRow + i;
            float4 v = make_float4(0.f, 0.f, 0.f, 0.f);
            if (r < M)
                v = *reinterpret_cast<const float4*>(&A[(long)r * lda + k0 + aCol4]);
            As[aCol4 + 0][aRow + i] = v.x;
            As[aCol4 + 1][aRow + i] = v.y;
            As[aCol4 + 2][aRow + i] = v.z;
            As[aCol4 + 3][aRow + i] = v.w;
        }
        // load B tile (BK x BN)
        #pragma unroll
        for (int i = 0; i < BK; i += 256 / (BN / 4)) {
            int c = colBase + bCol4;
            float4 v = make_float4(0.f, 0.f, 0.f, 0.f);
            if (c < N)   // N % 4 == 0 -> whole vector in range
                v = *reinterpret_cast<const float4*>(&B[(long)(k0 + bRow + i) * ldb + c]);
            *reinterpret_cast<float4*>(&Bs[bRow + i][bCol4]) = v;
        }
        __syncthreads();

        #pragma unroll
        for (int k = 0; k < BK; k++) {
            float regM[TM], regN[TN];
            #pragma unroll
            for (int i = 0; i < TM; i += 4)
                *reinterpret_cast<float4*>(&regM[i]) =
                    *reinterpret_cast<const float4*>(&As[k][tr * TM + i]);
            #pragma unroll
            for (int j = 0; j < TN; j += 4)
                *reinterpret_cast<float4*>(&regN[j]) =
                    *reinterpret_cast<const float4*>(&Bs[k][tc * TN + j]);
            #pragma unroll
            for (int i = 0; i < TM; i++)
                #pragma unroll
                for (int j = 0; j < TN; j++)
                    acc[i][j] += regM[i] * regN[j];
        }
        __syncthreads();
    }

    #pragma unroll
    for (int i = 0; i < TM; i++) {
        int r = rowBase + tr * TM + i;
        if (r >= M) continue;
        #pragma unroll
        for (int j = 0; j < TN; j++) {
            int c = colBase + tc * TN + j;
            if (c >= N) continue;
            long idx = (long)r * ldc + c;
            float v = acc[i][j];
            if (BIAS)  v += bias[c];
            if (RESID) v += ResB[idx];
            if (ACCUM) v += C[idx];
            if (RELU)  v = fmaxf(v, 0.f);
            C[idx] = v;
        }
    }
}

// ---------------- local-window attention ----------------
// grid: (25, 25, BB*HEADS), block: 64 threads (one per pixel of an 8x8 tile).
// Two passes over a shared 14x14 halo tile (K first -> logits in regs, then V).
__global__ __launch_bounds__(64)
void attn_kernel(const float* __restrict__ Qg0, const float* __restrict__ Kg0,
                 const float* __restrict__ Vg0, float* __restrict__ Og0)
{
    __shared__ float s[196][HD + 1];

    const int tid = threadIdx.x;
    const int tx = tid & 7, ty = tid >> 3;
    const int b  = blockIdx.z >> 3;
    const int hd = blockIdx.z & 7;
    const int h0 = blockIdx.y * 8, w0 = blockIdx.x * 8;

    const long chanBase = ((long)b * C3 + hd * HD) * HW;
    const float* Kg = Kg0 + chanBase;
    const float* Vg = Vg0 + chanBase;
    const float* Qg = Qg0 + chanBase;

    // --- pass 1: K halo into smem ---
    for (int i = tid; i < HD * 196; i += 64) {
        int c = i / 196, p = i % 196;
        int ph = h0 - PADW + p / 14;
        int pw = w0 - PADW + p % 14;
        ph = ph < 0 ? 0 : (ph > HH - 1 ? HH - 1 : ph);
        pw = pw < 0 ? 0 : (pw > WW2 - 1 ? WW2 - 1 : pw);
        s[p][c] = Kg[(long)c * HW + ph * WW2 + pw];
    }

    const int h = h0 + ty, w = w0 + tx;
    float q[HD];
    #pragma unroll
    for (int c = 0; c < HD; c++) q[c] = Qg[(long)c * HW + h * WW2 + w];
    __syncthreads();

    float lg[49];
    #pragma unroll
    for (int i = 0; i < WS; i++)
        #pragma unroll
        for (int j = 0; j < WS; j++) {
            int p = (ty + i) * 14 + (tx + j);
            float a = 0.f;
            #pragma unroll
            for (int c = 0; c < HD; c++) a += q[c] * s[p][c];
            lg[i * WS + j] = a * SCALE;
        }

    float m = lg[0];
    #pragma unroll
    for (int k = 1; k < 49; k++) m = fmaxf(m, lg[k]);
    float ssum = 0.f;
    #pragma unroll
    for (int k = 0; k < 49; k++) { lg[k] = __expf(lg[k] - m); ssum += lg[k]; }
    float inv = 1.f / ssum;
    #pragma unroll
    for (int k = 0; k < 49; k++) lg[k] *= inv;
    __syncthreads();

    // --- pass 2: V halo into same smem ---
    for (int i = tid; i < HD * 196; i += 64) {
        int c = i / 196, p = i % 196;
        int ph = h0 - PADW + p / 14;
        int pw = w0 - PADW + p % 14;
        ph = ph < 0 ? 0 : (ph > HH - 1 ? HH - 1 : ph);
        pw = pw < 0 ? 0 : (pw > WW2 - 1 ? WW2 - 1 : pw);
        s[p][c] = Vg[(long)c * HW + ph * WW2 + pw];
    }
    __syncthreads();

    float o[HD];
    #pragma unroll
    for (int c = 0; c < HD; c++) o[c] = 0.f;
    #pragma unroll
    for (int i = 0; i < WS; i++)
        #pragma unroll
        for (int j = 0; j < WS; j++) {
            int p = (ty + i) * 14 + (tx + j);
            float a = lg[i * WS + j];
            #pragma unroll
            for (int c = 0; c < HD; c++) o[c] += a * s[p][c];
        }

    float* Og = Og0 + chanBase + h * WW2 + w;
    #pragma unroll
    for (int c = 0; c < HD; c++) Og[(long)c * HW] = o[c];
}

// ---------------- LayerNorm 1: planar (B,C3,HW) -> row-major (N,C3) ----------------
// grid 2500, 256 threads, 32 pixels/block (HW % 32 == 0 -> never straddles batch)
__global__ __launch_bounds__(256)
void ln1_kernel(const float* __restrict__ T1, float* __restrict__ X,
                const float* __restrict__ g, const float* __restrict__ bta)
{
    __shared__ float s[C3][33];
    const int tid = threadIdx.x;
    const long base = (long)blockIdx.x * 32;
    const int b  = (int)(base / HW);
    const int n0 = (int)(base % HW);
    const float* Tb = T1 + (long)b * C3 * HW + n0;

    for (int i = tid; i < C3 * 32; i += 256) {
        int c = i >> 5, l = i & 31;
        s[c][l] = Tb[(long)c * HW + l];
    }
    __syncthreads();

    const int warp = tid >> 5, lane = tid & 31;
    for (int p = warp * 4; p < warp * 4 + 4; p++) {
        float sum = 0.f, sq = 0.f;
        #pragma unroll
        for (int k = 0; k < 8; k++) {
            float v = s[lane + 32 * k][p];
            sum += v; sq += v * v;
        }
        #pragma unroll
        for (int o = 16; o > 0; o >>= 1) {
            sum += __shfl_xor_sync(0xffffffffu, sum, o);
            sq  += __shfl_xor_sync(0xffffffffu, sq,  o);
        }
        float mu   = sum * (1.f / C3);
        float var  = sq * (1.f / C3) - mu * mu;
        float rstd = rsqrtf(var + LNEPS);
        float* Xr = X + (base + p) * (long)C3;
        #pragma unroll
        for (int k = 0; k < 8; k++) {
            int c = lane + 32 * k;
            Xr[c] = (s[c][p] - mu) * rstd * g[c] + bta[c];
        }
    }
}

// ---------------- LayerNorm 2: row-major (N,C3) -> planar (B,C3,HW) ----------------
__global__ __launch_bounds__(256)
void ln2_kernel(const float* __restrict__ Z, float* __restrict__ Out,
                const float* __restrict__ g, const float* __restrict__ bta)
{
    __shared__ float s[C3][33];
    const int tid = threadIdx.x;
    const long base = (long)blockIdx.x * 32;
    const int b  = (int)(base / HW);
    const int n0 = (int)(base % HW);

    for (int i = tid; i < 32 * C3; i += 256) {
        int p = i >> 8, c = i & 255;
        s[c][p] = Z[(base + p) * (long)C3 + c];
    }
    __syncthreads();

    const int warp = tid >> 5, lane = tid & 31;
    for (int p = warp * 4; p < warp * 4 + 4; p++) {
        float sum = 0.f, sq = 0.f;
        #pragma unroll
        for (int k = 0; k < 8; k++) {
            float v = s[lane + 32 * k][p];
            sum += v; sq += v * v;
        }
        #pragma unroll
        for (int o = 16; o > 0; o >>= 1) {
            sum += __shfl_xor_sync(0xffffffffu, sum, o);
            sq  += __shfl_xor_sync(0xffffffffu, sq,  o);
        }
        float mu   = sum * (1.f / C3);
        float var  = sq * (1.f / C3) - mu * mu;
        float rstd = rsqrtf(var + LNEPS);
        #pragma unroll
        for (int k = 0; k < 8; k++) {
            int c = lane + 32 * k;
            s[c][p] = (s[c][p] - mu) * rstd * g[c] + bta[c];
        }
    }
    __syncthreads();

    float* Ob = Out + (long)b * C3 * HW + n0;
    for (int i = tid; i < C3 * 32; i += 256) {
        int c = i >> 5, l = i & 31;
        Ob[(long)c * HW + l] = s[c][l];
    }
}

// ---------------- launch ----------------
extern "C" void kernel_launch(void* const* d_in, const int* in_sizes, int n_in,
                              void* d_out, int out_size)
{
    const float* F_lidar = (const float*)d_in[0];
    const float* F_cam   = (const float*)d_in[1];
    const float* Wq  = (const float*)d_in[2];
    const float* Wk  = (const float*)d_in[3];
    const float* Wv  = (const float*)d_in[4];
    const float* Wo  = (const float*)d_in[5];
    const float* Wr  = (const float*)d_in[6];
    const float* g1  = (const float*)d_in[7];
    const float* b1  = (const float*)d_in[8];
    const float* g2  = (const float*)d_in[9];
    const float* b2  = (const float*)d_in[10];
    const float* W1  = (const float*)d_in[11];
    const float* bf1 = (const float*)d_in[12];
    const float* W2  = (const float*)d_in[13];
    const float* bf2 = (const float*)d_in[14];
    float* out = (float*)d_out;

    float *Qb, *Kb, *Vb, *AOb, *T1b, *Xb, *Yb, *Zb;
    cudaGetSymbolAddress((void**)&Qb,  g_Q);
    cudaGetSymbolAddress((void**)&Kb,  g_K);
    cudaGetSymbolAddress((void**)&Vb,  g_V);
    cudaGetSymbolAddress((void**)&AOb, g_AO);
    cudaGetSymbolAddress((void**)&T1b, g_T1);
    cudaGetSymbolAddress((void**)&Xb,  g_X);
    cudaGetSymbolAddress((void**)&Yb,  g_Y);
    cudaGetSymbolAddress((void**)&Zb,  g_Z);

    const dim3 gridProj((HW + BN - 1) / BN, (C3 + BM - 1) / BM, BB);  // (313, 2, 2)

    // Q = Wq * F_lidar
    sgemm_kernel<16, false, false, false, false><<<gridProj, 256>>>(
        Wq, F_lidar, Qb, nullptr, nullptr,
        C3, HW, C1, C1, HW, HW, (long)C1 * HW, (long)C3 * HW);
    // K = Wk * F_cam
    sgemm_kernel<16, false, false, false, false><<<gridProj, 256>>>(
        Wk, F_cam, Kb, nullptr, nullptr,
        C3, HW, C2, C2, HW, HW, (long)C2 * HW, (long)C3 * HW);
    // V = Wv * F_cam
    sgemm_kernel<16, false, false, false, false><<<gridProj, 256>>>(
        Wv, F_cam, Vb, nullptr, nullptr,
        C3, HW, C2, C2, HW, HW, (long)C2 * HW, (long)C3 * HW);

    // local-window attention
    attn_kernel<<<dim3(WW2 / 8, HH / 8, BB * HEADS), 64>>>(Qb, Kb, Vb, AOb);

    // T1 = Wo * AO
    sgemm_kernel<16, false, false, false, false><<<gridProj, 256>>>(
        Wo, AOb, T1b, nullptr, nullptr,
        C3, HW, C3, C3, HW, HW, (long)C3 * HW, (long)C3 * HW);
    // T1 += Wr * F_lidar
    sgemm_kernel<16, true, false, false, false><<<gridProj, 256>>>(
        Wr, F_lidar, T1b, nullptr, nullptr,
        C3, HW, C1, C1, HW, HW, (long)C1 * HW, (long)C3 * HW);

    // X = LN1(T1), with NCHW -> (N, C) transpose
    ln1_kernel<<<NPIX / 32, 256>>>(T1b, Xb, g1, b1);

    // Y = relu(X * W1 + bf1)
    sgemm_kernel<16, false, true, true, false><<<dim3(CF / BN, NPIX / BM, 1), 256>>>(
        Xb, W1, Yb, bf1, nullptr,
        NPIX, CF, C3, C3, CF, CF, 0, 0);

    // Z = Y * W2 + bf2 + X
    sgemm_kernel<16, false, true, false, true><<<dim3(C3 / BN, NPIX / BM, 1), 256>>>(
        Yb, W2, Zb, bf2, Xb,
        NPIX, C3, CF, CF, C3, C3, 0, 0);

    // out = LN2(Z), with (N, C) -> NCHW transpose
    ln2_kernel<<<NPIX / 32, 256>>>(Zb, out, g2, b2);
}

// round 2
// speedup vs baseline: 2.2273x; 2.2273x over previous
#include <cuda_runtime.h>
#include <cuda_bf16.h>
#include <math.h>
#include <stdint.h>

// ---------------- problem constants ----------------
#define BB    2
#define C1    64
#define C2    256
#define C3    256
#define HH    200
#define WW2   200
#define HW    40000        // HH*WW2
#define NPIX  80000        // BB*HW
#define HEADS 8
#define HD    32           // C3/HEADS
#define WS    7
#define PADW  3
#define CF    1024         // 4*C3
#define SCALE 0.17677669529663689f   // HD^-0.5
#define LNEPS 1e-5f

// ---------------- scratch (device globals; no runtime allocation) ----------------
__device__ float g_Q [(long)BB*C3*HW];
__device__ float g_K [(long)BB*C3*HW];
__device__ float g_V [(long)BB*C3*HW];
__device__ float g_AO[(long)BB*C3*HW];
__device__ float g_T1[(long)BB*C3*HW];
__device__ float g_X [(long)NPIX*C3];
__device__ float g_Y [(long)NPIX*CF];
__device__ float g_Z [(long)NPIX*C3];

// ---------------- tf32 helpers ----------------
__device__ __forceinline__ float to_tf32(float x) {
    uint32_t u;
    asm("cvt.rna.tf32.f32 %0, %1;" : "=r"(u) : "f"(x));
    return __uint_as_float(u);
}

__device__ __forceinline__ void mma_tf32(float* c, const uint32_t* a, const uint32_t* b) {
    asm volatile(
        "mma.sync.aligned.m16n8k8.row.col.f32.tf32.tf32.f32 "
        "{%0,%1,%2,%3},{%4,%5,%6,%7},{%8,%9},{%0,%1,%2,%3};"
        : "+f"(c[0]), "+f"(c[1]), "+f"(c[2]), "+f"(c[3])
        : "r"(a[0]), "r"(a[1]), "r"(a[2]), "r"(a[3]), "r"(b[0]), "r"(b[1]));
}

// ---------------- tensor-core GEMM (tf32 mma.sync) ----------------
// C[M,N] = A[M,K](row, lda) * B[K,N](row, ldb)  [+ C][+ bias[col]][+ Res][relu]
// batched over gridDim.z via strideB/strideC. Requires K%16==0, N%4==0, M%8==0.
#define BM 128
#define BN 128
#define BKT 16

template<bool ACCUM, bool BIAS, bool RELU, bool RESID>
__global__ __launch_bounds__(256, 2)
void tgemm_kernel(const float* __restrict__ A, const float* __restrict__ B,
                  float* __restrict__ C, const float* __restrict__ bias,
                  const float* __restrict__ Res,
                  int M, int N, int K, int lda, int ldb, int ldc,
                  long strideB, long strideC)
{
    B += (long)blockIdx.z * strideB;
    C += (long)blockIdx.z * strideC;
    const float* ResB = RESID ? (Res + (long)blockIdx.z * strideC) : nullptr;

    __shared__ float As[2][BM][BKT + 4];    // stride 20: frag banks 4m+k, conflict-free
    __shared__ float Bs[2][BKT][BN + 8];    // stride 136: frag banks 8k+n, conflict-free

    const int tid  = threadIdx.x;
    const int lane = tid & 31;
    const int warp = tid >> 5;
    const int warpM = (warp >> 2) * 64;     // 2 warps in M
    const int warpN = (warp & 3) * 32;      // 4 warps in N
    const int lr = lane >> 2;               // 0..7
    const int lc = lane & 3;                // 0..3

    const int rowBase = blockIdx.y * BM;
    const int colBase = blockIdx.x * BN;

    // global-load mapping
    const int aR  = tid >> 2;               // 0..63 (+64)
    const int aK4 = (tid & 3) * 4;
    const int bK  = tid >> 5;               // 0..7 (+8)
    const int bC4 = (tid & 31) * 4;

    float acc[4][4][4];
    #pragma unroll
    for (int i = 0; i < 4; i++)
        #pragma unroll
        for (int j = 0; j < 4; j++)
            #pragma unroll
            for (int e = 0; e < 4; e++) acc[i][j][e] = 0.f;

    const int numT = K / BKT;
    float4 pa[2], pb[2];

    // prefetch tile 0
    {
        #pragma unroll
        for (int u = 0; u < 2; u++) {
            int r = rowBase + aR + 64 * u;
            pa[u] = (r < M) ? *reinterpret_cast<const float4*>(&A[(long)r * lda + aK4])
                            : make_float4(0.f, 0.f, 0.f, 0.f);
            int c = colBase + bC4;
            pb[u] = (c < N) ? *reinterpret_cast<const float4*>(&B[(long)(bK + 8 * u) * ldb + c])
                            : make_float4(0.f, 0.f, 0.f, 0.f);
        }
        #pragma unroll
        for (int u = 0; u < 2; u++) {
            As[0][aR + 64 * u][aK4 + 0] = to_tf32(pa[u].x);
            As[0][aR + 64 * u][aK4 + 1] = to_tf32(pa[u].y);
            As[0][aR + 64 * u][aK4 + 2] = to_tf32(pa[u].z);
            As[0][aR + 64 * u][aK4 + 3] = to_tf32(pa[u].w);
            Bs[0][bK + 8 * u][bC4 + 0] = to_tf32(pb[u].x);
            Bs[0][bK + 8 * u][bC4 + 1] = to_tf32(pb[u].y);
            Bs[0][bK + 8 * u][bC4 + 2] = to_tf32(pb[u].z);
            Bs[0][bK + 8 * u][bC4 + 3] = to_tf32(pb[u].w);
        }
    }
    __syncthreads();

    for (int t = 0; t < numT; t++) {
        const int cur = t & 1, nxt = cur ^ 1;
        const int k0n = (t + 1) * BKT;

        if (t + 1 < numT) {
            #pragma unroll
            for (int u = 0; u < 2; u++) {
                int r = rowBase + aR + 64 * u;
                pa[u] = (r < M) ? *reinterpret_cast<const float4*>(&A[(long)r * lda + k0n + aK4])
                                : make_float4(0.f, 0.f, 0.f, 0.f);
                int c = colBase + bC4;
                pb[u] = (c < N) ? *reinterpret_cast<const float4*>(&B[(long)(k0n + bK + 8 * u) * ldb + c])
                                : make_float4(0.f, 0.f, 0.f, 0.f);
            }
        }

        #pragma unroll
        for (int kk = 0; kk < BKT; kk += 8) {
            uint32_t af[4][4], bf[4][2];
            #pragma unroll
            for (int ti = 0; ti < 4; ti++) {
                int m = warpM + 16 * ti;
                af[ti][0] = __float_as_uint(As[cur][m + lr    ][kk + lc    ]);
                af[ti][1] = __float_as_uint(As[cur][m + lr + 8][kk + lc    ]);
                af[ti][2] = __float_as_uint(As[cur][m + lr    ][kk + lc + 4]);
                af[ti][3] = __float_as_uint(As[cur][m + lr + 8][kk + lc + 4]);
            }
            #pragma unroll
            for (int tj = 0; tj < 4; tj++) {
                int n = warpN + 8 * tj;
                bf[tj][0] = __float_as_uint(Bs[cur][kk + lc    ][n + lr]);
                bf[tj][1] = __float_as_uint(Bs[cur][kk + lc + 4][n + lr]);
            }
            #pragma unroll
            for (int ti = 0; ti < 4; ti++)
                #pragma unroll
                for (int tj = 0; tj < 4; tj++)
                    mma_tf32(acc[ti][tj], af[ti], bf[tj]);
        }

        if (t + 1 < numT) {
            #pragma unroll
            for (int u = 0; u < 2; u++) {
                As[nxt][aR + 64 * u][aK4 + 0] = to_tf32(pa[u].x);
                As[nxt][aR + 64 * u][aK4 + 1] = to_tf32(pa[u].y);
                As[nxt][aR + 64 * u][aK4 + 2] = to_tf32(pa[u].z);
                As[nxt][aR + 64 * u][aK4 + 3] = to_tf32(pa[u].w);
                Bs[nxt][bK + 8 * u][bC4 + 0] = to_tf32(pb[u].x);
                Bs[nxt][bK + 8 * u][bC4 + 1] = to_tf32(pb[u].y);
                Bs[nxt][bK + 8 * u][bC4 + 2] = to_tf32(pb[u].z);
                Bs[nxt][bK + 8 * u][bC4 + 3] = to_tf32(pb[u].w);
            }
        }
        __syncthreads();
    }

    // epilogue: c0,c1 at (row=lr, col=2*lc,2*lc+1), c2,c3 at row lr+8
    #pragma unroll
    for (int ti = 0; ti < 4; ti++) {
        #pragma unroll
        for (int h = 0; h < 2; h++) {
            int r = rowBase + warpM + 16 * ti + lr + 8 * h;
            if (r >= M) continue;
            #pragma unroll
            for (int tj = 0; tj < 4; tj++) {
                int c = colBase + warpN + 8 * tj + 2 * lc;
                if (c >= N) continue;
                long idx = (long)r * ldc + c;
                float v0 = acc[ti][tj][2 * h + 0];
                float v1 = acc[ti][tj][2 * h + 1];
                if (BIAS)  { v0 += bias[c]; v1 += bias[c + 1]; }
                if (RESID) { float2 rr = *reinterpret_cast<const float2*>(&ResB[idx]);
                             v0 += rr.x; v1 += rr.y; }
                if (ACCUM) { float2 cc = *reinterpret_cast<const float2*>(&C[idx]);
                             v0 += cc.x; v1 += cc.y; }
                if (RELU)  { v0 = fmaxf(v0, 0.f); v1 = fmaxf(v1, 0.f); }
                *reinterpret_cast<float2*>(&C[idx]) = make_float2(v0, v1);
            }
        }
    }
}

// ---------------- local-window attention ----------------
__global__ __launch_bounds__(64)
void attn_kernel(const float* __restrict__ Qg0, const float* __restrict__ Kg0,
                 const float* __restrict__ Vg0, float* __restrict__ Og0)
{
    __shared__ float s[196][HD + 1];

    const int tid = threadIdx.x;
    const int tx = tid & 7, ty = tid >> 3;
    const int b  = blockIdx.z >> 3;
    const int hd = blockIdx.z & 7;
    const int h0 = blockIdx.y * 8, w0 = blockIdx.x * 8;

    const long chanBase = ((long)b * C3 + hd * HD) * HW;
    const float* Kg = Kg0 + chanBase;
    const float* Vg = Vg0 + chanBase;
    const float* Qg = Qg0 + chanBase;

    for (int i = tid; i < HD * 196; i += 64) {
        int c = i / 196, p = i % 196;
        int ph = h0 - PADW + p / 14;
        int pw = w0 - PADW + p % 14;
        ph = ph < 0 ? 0 : (ph > HH - 1 ? HH - 1 : ph);
        pw = pw < 0 ? 0 : (pw > WW2 - 1 ? WW2 - 1 : pw);
        s[p][c] = Kg[(long)c * HW + ph * WW2 + pw];
    }

    const int h = h0 + ty, w = w0 + tx;
    float q[HD];
    #pragma unroll
    for (int c = 0; c < HD; c++) q[c] = Qg[(long)c * HW + h * WW2 + w];
    __syncthreads();

    float lg[49];
    #pragma unroll
    for (int i = 0; i < WS; i++)
        #pragma unroll
        for (int j = 0; j < WS; j++) {
            int p = (ty + i) * 14 + (tx + j);
            float a = 0.f;
            #pragma unroll
            for (int c = 0; c < HD; c++) a += q[c] * s[p][c];
            lg[i * WS + j] = a * SCALE;
        }

    float m = lg[0];
    #pragma unroll
    for (int k = 1; k < 49; k++) m = fmaxf(m, lg[k]);
    float ssum = 0.f;
    #pragma unroll
    for (int k = 0; k < 49; k++) { lg[k] = __expf(lg[k] - m); ssum += lg[k]; }
    float inv = 1.f / ssum;
    #pragma unroll
    for (int k = 0; k < 49; k++) lg[k] *= inv;
    __syncthreads();

    for (int i = tid; i < HD * 196; i += 64) {
        int c = i / 196, p = i % 196;
        int ph = h0 - PADW + p / 14;
        int pw = w0 - PADW + p % 14;
        ph = ph < 0 ? 0 : (ph > HH - 1 ? HH - 1 : ph);
        pw = pw < 0 ? 0 : (pw > WW2 - 1 ? WW2 - 1 : pw);
        s[p][c] = Vg[(long)c * HW + ph * WW2 + pw];
    }
    __syncthreads();

    float o[HD];
    #pragma unroll
    for (int c = 0; c < HD; c++) o[c] = 0.f;
    #pragma unroll
    for (int i = 0; i < WS; i++)
        #pragma unroll
        for (int j = 0; j < WS; j++) {
            int p = (ty + i) * 14 + (tx + j);
            float a = lg[i * WS + j];
            #pragma unroll
            for (int c = 0; c < HD; c++) o[c] += a * s[p][c];
        }

    float* Og = Og0 + chanBase + h * WW2 + w;
    #pragma unroll
    for (int c = 0; c < HD; c++) Og[(long)c * HW] = o[c];
}

// ---------------- LayerNorm 1: planar (B,C3,HW) -> row-major (N,C3) ----------------
__global__ __launch_bounds__(256)
void ln1_kernel(const float* __restrict__ T1, float* __restrict__ X,
                const float* __restrict__ g, const float* __restrict__ bta)
{
    __shared__ float s[C3][33];
    const int tid = threadIdx.x;
    const long base = (long)blockIdx.x * 32;
    const int b  = (int)(base / HW);
    const int n0 = (int)(base % HW);
    const float* Tb = T1 + (long)b * C3 * HW + n0;

    for (int i = tid; i < C3 * 32; i += 256) {
        int c = i >> 5, l = i & 31;
        s[c][l] = Tb[(long)c * HW + l];
    }
    __syncthreads();

    const int warp = tid >> 5, lane = tid & 31;
    for (int p = warp * 4; p < warp * 4 + 4; p++) {
        float sum = 0.f, sq = 0.f;
        #pragma unroll
        for (int k = 0; k < 8; k++) {
            float v = s[lane + 32 * k][p];
            sum += v; sq += v * v;
        }
        #pragma unroll
        for (int o = 16; o > 0; o >>= 1) {
            sum += __shfl_xor_sync(0xffffffffu, sum, o);
            sq  += __shfl_xor_sync(0xffffffffu, sq,  o);
        }
        float mu   = sum * (1.f / C3);
        float var  = sq * (1.f / C3) - mu * mu;
        float rstd = rsqrtf(var + LNEPS);
        float* Xr = X + (base + p) * (long)C3;
        #pragma unroll
        for (int k = 0; k < 8; k++) {
            int c = lane + 32 * k;
            Xr[c] = (s[c][p] - mu) * rstd * g[c] + bta[c];
        }
    }
}

// ---------------- LayerNorm 2: row-major (N,C3) -> planar (B,C3,HW) ----------------
__global__ __launch_bounds__(256)
void ln2_kernel(const float* __restrict__ Z, float* __restrict__ Out,
                const float* __restrict__ g, const float* __restrict__ bta)
{
    __shared__ float s[C3][33];
    const int tid = threadIdx.x;
    const long base = (long)blockIdx.x * 32;
    const int b  = (int)(base / HW);
    const int n0 = (int)(base % HW);

    for (int i = tid; i < 32 * C3; i += 256) {
        int p = i >> 8, c = i & 255;
        s[c][p] = Z[(base + p) * (long)C3 + c];
    }
    __syncthreads();

    const int warp = tid >> 5, lane = tid & 31;
    for (int p = warp * 4; p < warp * 4 + 4; p++) {
        float sum = 0.f, sq = 0.f;
        #pragma unroll
        for (int k = 0; k < 8; k++) {
            float v = s[lane + 32 * k][p];
            sum += v; sq += v * v;
        }
        #pragma unroll
        for (int o = 16; o > 0; o >>= 1) {
            sum += __shfl_xor_sync(0xffffffffu, sum, o);
            sq  += __shfl_xor_sync(0xffffffffu, sq,  o);
        }
        float mu   = sum * (1.f / C3);
        float var  = sq * (1.f / C3) - mu * mu;
        float rstd = rsqrtf(var + LNEPS);
        #pragma unroll
        for (int k = 0; k < 8; k++) {
            int c = lane + 32 * k;
            s[c][p] = (s[c][p] - mu) * rstd * g[c] + bta[c];
        }
    }
    __syncthreads();

    float* Ob = Out + (long)b * C3 * HW + n0;
    for (int i = tid; i < C3 * 32; i += 256) {
        int c = i >> 5, l = i & 31;
        Ob[(long)c * HW + l] = s[c][l];
    }
}

// ---------------- launch ----------------
extern "C" void kernel_launch(void* const* d_in, const int* in_sizes, int n_in,
                              void* d_out, int out_size)
{
    const float* F_lidar = (const float*)d_in[0];
    const float* F_cam   = (const float*)d_in[1];
    const float* Wq  = (const float*)d_in[2];
    const float* Wk  = (const float*)d_in[3];
    const float* Wv  = (const float*)d_in[4];
    const float* Wo  = (const float*)d_in[5];
    const float* Wr  = (const float*)d_in[6];
    const float* g1  = (const float*)d_in[7];
    const float* b1  = (const float*)d_in[8];
    const float* g2  = (const float*)d_in[9];
    const float* b2  = (const float*)d_in[10];
    const float* W1  = (const float*)d_in[11];
    const float* bf1 = (const float*)d_in[12];
    const float* W2  = (const float*)d_in[13];
    const float* bf2 = (const float*)d_in[14];
    float* out = (float*)d_out;

    float *Qb, *Kb, *Vb, *AOb, *T1b, *Xb, *Yb, *Zb;
    cudaGetSymbolAddress((void**)&Qb,  g_Q);
    cudaGetSymbolAddress((void**)&Kb,  g_K);
    cudaGetSymbolAddress((void**)&Vb,  g_V);
    cudaGetSymbolAddress((void**)&AOb, g_AO);
    cudaGetSymbolAddress((void**)&T1b, g_T1);
    cudaGetSymbolAddress((void**)&Xb,  g_X);
    cudaGetSymbolAddress((void**)&Yb,  g_Y);
    cudaGetSymbolAddress((void**)&Zb,  g_Z);

    const dim3 gridProj((HW + BN - 1) / BN, C3 / BM, BB);   // (313, 2, 2)

    // Q = Wq * F_lidar
    tgemm_kernel<false, false, false, false><<<gridProj, 256>>>(
        Wq, F_lidar, Qb, nullptr, nullptr,
        C3, HW, C1, C1, HW, HW, (long)C1 * HW, (long)C3 * HW);
    // K = Wk * F_cam
    tgemm_kernel<false, false, false, false><<<gridProj, 256>>>(
        Wk, F_cam, Kb, nullptr, nullptr,
        C3, HW, C2, C2, HW, HW, (long)C2 * HW, (long)C3 * HW);
    // V = Wv * F_cam
    tgemm_kernel<false, false, false, false><<<gridProj, 256>>>(
        Wv, F_cam, Vb, nullptr, nullptr,
        C3, HW, C2, C2, HW, HW, (long)C2 * HW, (long)C3 * HW);

    // local-window attention
    attn_kernel<<<dim3(WW2 / 8, HH / 8, BB * HEADS), 64>>>(Qb, Kb, Vb, AOb);

    // T1 = Wo * AO
    tgemm_kernel<false, false, false, false><<<gridProj, 256>>>(
        Wo, AOb, T1b, nullptr, nullptr,
        C3, HW, C3, C3, HW, HW, (long)C3 * HW, (long)C3 * HW);
    // T1 += Wr * F_lidar
    tgemm_kernel<true, false, false, false><<<gridProj, 256>>>(
        Wr, F_lidar, T1b, nullptr, nullptr,
        C3, HW, C1, C1, HW, HW, (long)C1 * HW, (long)C3 * HW);

    // X = LN1(T1), NCHW -> (N, C)
    ln1_kernel<<<NPIX / 32, 256>>>(T1b, Xb, g1, b1);

    // Y = relu(X * W1 + bf1)
    tgemm_kernel<false, true, true, false><<<dim3(CF / BN, NPIX / BM, 1), 256>>>(
        Xb, W1, Yb, bf1, nullptr,
        NPIX, CF, C3, C3, CF, CF, 0, 0);

    // Z = Y * W2 + bf2 + X
    tgemm_kernel<false, true, false, true><<<dim3(C3 / BN, NPIX / BM, 1), 256>>>(
        Yb, W2, Zb, bf2, Xb,
        NPIX, C3, CF, CF, C3, C3, 0, 0);

    // out = LN2(Z), (N, C) -> NCHW
    ln2_kernel<<<NPIX / 32, 256>>>(Zb, out, g2, b2);
}

// round 3
// speedup vs baseline: 2.4997x; 1.1223x over previous
#include <cuda_runtime.h>
#include <cuda_bf16.h>
#include <math.h>
#include <stdint.h>

// ---------------- problem constants ----------------
#define BB    2
#define C1    64
#define C2    256
#define C3    256
#define HH    200
#define WW2   200
#define HW    40000        // HH*WW2
#define NPIX  80000        // BB*HW
#define HEADS 8
#define HD    32           // C3/HEADS
#define WS    7
#define PADW  3
#define CF    1024         // 4*C3
#define SCALE 0.17677669529663689f   // HD^-0.5
#define LNEPS 1e-5f

// ---------------- scratch (device globals; no runtime allocation) ----------------
__device__ float g_Q [(long)BB*C3*HW];
__device__ float g_K [(long)BB*C3*HW];
__device__ float g_V [(long)BB*C3*HW];
__device__ float g_AO[(long)BB*C3*HW];
__device__ float g_T1[(long)BB*C3*HW];
__device__ float g_X [(long)NPIX*C3];
__device__ float g_Y [(long)NPIX*CF];
__device__ float g_Z [(long)NPIX*C3];

// ---------------- tf32 helpers ----------------
__device__ __forceinline__ float to_tf32(float x) {
    uint32_t u;
    asm("cvt.rna.tf32.f32 %0, %1;" : "=r"(u) : "f"(x));
    return __uint_as_float(u);
}

__device__ __forceinline__ void mma_tf32(float* c, const uint32_t* a, const uint32_t* b) {
    asm volatile(
        "mma.sync.aligned.m16n8k8.row.col.f32.tf32.tf32.f32 "
        "{%0,%1,%2,%3},{%4,%5,%6,%7},{%8,%9},{%0,%1,%2,%3};"
        : "+f"(c[0]), "+f"(c[1]), "+f"(c[2]), "+f"(c[3])
        : "r"(a[0]), "r"(a[1]), "r"(a[2]), "r"(a[3]), "r"(b[0]), "r"(b[1]));
}

// ---------------- tensor-core GEMM (tf32 mma.sync) ----------------
#define BM 128
#define BN 128
#define BKT 16

template<bool ACCUM, bool BIAS, bool RELU, bool RESID>
__global__ __launch_bounds__(256, 2)
void tgemm_kernel(const float* __restrict__ A, const float* __restrict__ B,
                  float* __restrict__ C, const float* __restrict__ bias,
                  const float* __restrict__ Res,
                  int M, int N, int K, int lda, int ldb, int ldc,
                  long strideB, long strideC)
{
    B += (long)blockIdx.z * strideB;
    C += (long)blockIdx.z * strideC;
    const float* ResB = RESID ? (Res + (long)blockIdx.z * strideC) : nullptr;

    __shared__ float As[2][BM][BKT + 4];
    __shared__ float Bs[2][BKT][BN + 8];

    const int tid  = threadIdx.x;
    const int lane = tid & 31;
    const int warp = tid >> 5;
    const int warpM = (warp >> 2) * 64;
    const int warpN = (warp & 3) * 32;
    const int lr = lane >> 2;
    const int lc = lane & 3;

    const int rowBase = blockIdx.y * BM;
    const int colBase = blockIdx.x * BN;

    const int aR  = tid >> 2;
    const int aK4 = (tid & 3) * 4;
    const int bK  = tid >> 5;
    const int bC4 = (tid & 31) * 4;

    float acc[4][4][4];
    #pragma unroll
    for (int i = 0; i < 4; i++)
        #pragma unroll
        for (int j = 0; j < 4; j++)
            #pragma unroll
            for (int e = 0; e < 4; e++) acc[i][j][e] = 0.f;

    const int numT = K / BKT;
    float4 pa[2], pb[2];

    {
        #pragma unroll
        for (int u = 0; u < 2; u++) {
            int r = rowBase + aR + 64 * u;
            pa[u] = (r < M) ? *reinterpret_cast<const float4*>(&A[(long)r * lda + aK4])
                            : make_float4(0.f, 0.f, 0.f, 0.f);
            int c = colBase + bC4;
            pb[u] = (c < N) ? *reinterpret_cast<const float4*>(&B[(long)(bK + 8 * u) * ldb + c])
                            : make_float4(0.f, 0.f, 0.f, 0.f);
        }
        #pragma unroll
        for (int u = 0; u < 2; u++) {
            As[0][aR + 64 * u][aK4 + 0] = to_tf32(pa[u].x);
            As[0][aR + 64 * u][aK4 + 1] = to_tf32(pa[u].y);
            As[0][aR + 64 * u][aK4 + 2] = to_tf32(pa[u].z);
            As[0][aR + 64 * u][aK4 + 3] = to_tf32(pa[u].w);
            Bs[0][bK + 8 * u][bC4 + 0] = to_tf32(pb[u].x);
            Bs[0][bK + 8 * u][bC4 + 1] = to_tf32(pb[u].y);
            Bs[0][bK + 8 * u][bC4 + 2] = to_tf32(pb[u].z);
            Bs[0][bK + 8 * u][bC4 + 3] = to_tf32(pb[u].w);
        }
    }
    __syncthreads();

    for (int t = 0; t < numT; t++) {
        const int cur = t & 1, nxt = cur ^ 1;
        const int k0n = (t + 1) * BKT;

        if (t + 1 < numT) {
            #pragma unroll
            for (int u = 0; u < 2; u++) {
                int r = rowBase + aR + 64 * u;
                pa[u] = (r < M) ? *reinterpret_cast<const float4*>(&A[(long)r * lda + k0n + aK4])
                                : make_float4(0.f, 0.f, 0.f, 0.f);
                int c = colBase + bC4;
                pb[u] = (c < N) ? *reinterpret_cast<const float4*>(&B[(long)(k0n + bK + 8 * u) * ldb + c])
                                : make_float4(0.f, 0.f, 0.f, 0.f);
            }
        }

        #pragma unroll
        for (int kk = 0; kk < BKT; kk += 8) {
            uint32_t af[4][4], bf[4][2];
            #pragma unroll
            for (int ti = 0; ti < 4; ti++) {
                int m = warpM + 16 * ti;
                af[ti][0] = __float_as_uint(As[cur][m + lr    ][kk + lc    ]);
                af[ti][1] = __float_as_uint(As[cur][m + lr + 8][kk + lc    ]);
                af[ti][2] = __float_as_uint(As[cur][m + lr    ][kk + lc + 4]);
                af[ti][3] = __float_as_uint(As[cur][m + lr + 8][kk + lc + 4]);
            }
            #pragma unroll
            for (int tj = 0; tj < 4; tj++) {
                int n = warpN + 8 * tj;
                bf[tj][0] = __float_as_uint(Bs[cur][kk + lc    ][n + lr]);
                bf[tj][1] = __float_as_uint(Bs[cur][kk + lc + 4][n + lr]);
            }
            #pragma unroll
            for (int ti = 0; ti < 4; ti++)
                #pragma unroll
                for (int tj = 0; tj < 4; tj++)
                    mma_tf32(acc[ti][tj], af[ti], bf[tj]);
        }

        if (t + 1 < numT) {
            #pragma unroll
            for (int u = 0; u < 2; u++) {
                As[nxt][aR + 64 * u][aK4 + 0] = to_tf32(pa[u].x);
                As[nxt][aR + 64 * u][aK4 + 1] = to_tf32(pa[u].y);
                As[nxt][aR + 64 * u][aK4 + 2] = to_tf32(pa[u].z);
                As[nxt][aR + 64 * u][aK4 + 3] = to_tf32(pa[u].w);
                Bs[nxt][bK + 8 * u][bC4 + 0] = to_tf32(pb[u].x);
                Bs[nxt][bK + 8 * u][bC4 + 1] = to_tf32(pb[u].y);
                Bs[nxt][bK + 8 * u][bC4 + 2] = to_tf32(pb[u].z);
                Bs[nxt][bK + 8 * u][bC4 + 3] = to_tf32(pb[u].w);
            }
        }
        __syncthreads();
    }

    #pragma unroll
    for (int ti = 0; ti < 4; ti++) {
        #pragma unroll
        for (int h = 0; h < 2; h++) {
            int r = rowBase + warpM + 16 * ti + lr + 8 * h;
            if (r >= M) continue;
            #pragma unroll
            for (int tj = 0; tj < 4; tj++) {
                int c = colBase + warpN + 8 * tj + 2 * lc;
                if (c >= N) continue;
                long idx = (long)r * ldc + c;
                float v0 = acc[ti][tj][2 * h + 0];
                float v1 = acc[ti][tj][2 * h + 1];
                if (BIAS)  { v0 += bias[c]; v1 += bias[c + 1]; }
                if (RESID) { float2 rr = *reinterpret_cast<const float2*>(&ResB[idx]);
                             v0 += rr.x; v1 += rr.y; }
                if (ACCUM) { float2 cc = *reinterpret_cast<const float2*>(&C[idx]);
                             v0 += cc.x; v1 += cc.y; }
                if (RELU)  { v0 = fmaxf(v0, 0.f); v1 = fmaxf(v1, 0.f); }
                *reinterpret_cast<float2*>(&C[idx]) = make_float2(v0, v1);
            }
        }
    }
}

// ---------------- local-window attention (bf16 smem, channel-split) ----------------
// Block: 128 threads = 4 warps. Tile: 8x8 pixels, 2 threads per pixel
// (lane<16 -> channels 0..15, lane>=16 -> channels 16..31; combine via shfl_xor 16).
// Halo 14x14 stored as bf162 [196][20] (stride 20 -> conflict-free LDS.128).
#define SROW 20   // bf162 per halo row (16 data + 4 pad)

__global__ __launch_bounds__(128, 5)
void attn_kernel(const float* __restrict__ Qg0, const float* __restrict__ Kg0,
                 const float* __restrict__ Vg0, float* __restrict__ Og0)
{
    __shared__ __nv_bfloat162 s[196 * SROW];

    const int tid  = threadIdx.x;
    const int lane = tid & 31;
    const int warp = tid >> 5;
    const int half = lane >> 4;                 // channel half
    const int pix  = warp * 16 + (lane & 15);   // 0..63
    const int tx = pix & 7, ty = pix >> 3;

    const int b  = blockIdx.z >> 3;
    const int hd = blockIdx.z & 7;
    const int h0 = blockIdx.y * 8, w0 = blockIdx.x * 8;

    const long chanBase = ((long)b * C3 + hd * HD) * HW;
    const float* Kg = Kg0 + chanBase;
    const float* Vg = Vg0 + chanBase;
    const float* Qg = Qg0 + chanBase;

    // ---- fill K halo (bf16) ----
    for (int i = tid; i < 16 * 196; i += 128) {
        int cp = i / 196, p = i % 196;          // cp = channel pair 0..15
        int ph = h0 - PADW + p / 14;
        int pw = w0 - PADW + p % 14;
        ph = ph < 0 ? 0 : (ph > HH - 1 ? HH - 1 : ph);
        pw = pw < 0 ? 0 : (pw > WW2 - 1 ? WW2 - 1 : pw);
        long off = (long)(2 * cp) * HW + ph * WW2 + pw;
        s[p * SROW + cp] = __floats2bfloat162_rn(Kg[off], Kg[off + HW]);
    }

    // ---- load Q half (16 channels) ----
    const int h = h0 + ty, w = w0 + tx;
    const long poff = (long)h * WW2 + w;
    float q[16];
    #pragma unroll
    for (int c = 0; c < 16; c++)
        q[c] = Qg[(long)(half * 16 + c) * HW + poff];
    __syncthreads();

    // ---- logits: partial dot over this thread's 16 channels ----
    float lg[49];
    {
        const __nv_bfloat162* sp = s + half * 8;
        #pragma unroll
        for (int i = 0; i < WS; i++) {
            const __nv_bfloat162* row = sp + ((ty + i) * 14 + tx) * SROW;
            #pragma unroll
            for (int j = 0; j < WS; j++) {
                float4 u = *reinterpret_cast<const float4*>(row);
                float4 v = *reinterpret_cast<const float4*>(row + 4);
                row += SROW;
                const __nv_bfloat162* a = reinterpret_cast<const __nv_bfloat162*>(&u);
                const __nv_bfloat162* bb = reinterpret_cast<const __nv_bfloat162*>(&v);
                float acc = 0.f;
                #pragma unroll
                for (int c = 0; c < 4; c++) {
                    float2 f0 = __bfloat1622float2(a[c]);
                    float2 f1 = __bfloat1622float2(bb[c]);
                    acc += q[2 * c] * f0.x + q[2 * c + 1] * f0.y;
                    acc += q[8 + 2 * c] * f1.x + q[8 + 2 * c + 1] * f1.y;
                }
                lg[i * WS + j] = acc;
            }
        }
    }

    // combine channel halves + scale
    #pragma unroll
    for (int k = 0; k < 49; k++)
        lg[k] = (lg[k] + __shfl_xor_sync(0xffffffffu, lg[k], 16)) * SCALE;

    // softmax (identical in both halves)
    float m = lg[0];
    #pragma unroll
    for (int k = 1; k < 49; k++) m = fmaxf(m, lg[k]);
    float ssum = 0.f;
    #pragma unroll
    for (int k = 0; k < 49; k++) { lg[k] = __expf(lg[k] - m); ssum += lg[k]; }
    float inv = 1.f / ssum;
    #pragma unroll
    for (int k = 0; k < 49; k++) lg[k] *= inv;
    __syncthreads();

    // ---- fill V halo (bf16) ----
    for (int i = tid; i < 16 * 196; i += 128) {
        int cp = i / 196, p = i % 196;
        int ph = h0 - PADW + p / 14;
        int pw = w0 - PADW + p % 14;
        ph = ph < 0 ? 0 : (ph > HH - 1 ? HH - 1 : ph);
        pw = pw < 0 ? 0 : (pw > WW2 - 1 ? WW2 - 1 : pw);
        long off = (long)(2 * cp) * HW + ph * WW2 + pw;
        s[p * SROW + cp] = __floats2bfloat162_rn(Vg[off], Vg[off + HW]);
    }
    __syncthreads();

    // ---- AV: this thread's 16 channels ----
    float o[16];
    #pragma unroll
    for (int c = 0; c < 16; c++) o[c] = 0.f;
    {
        const __nv_bfloat162* sp = s + half * 8;
        #pragma unroll
        for (int i = 0; i < WS; i++) {
            const __nv_bfloat162* row = sp + ((ty + i) * 14 + tx) * SROW;
            #pragma unroll
            for (int j = 0; j < WS; j++) {
                float a = lg[i * WS + j];
                float4 u = *reinterpret_cast<const float4*>(row);
                float4 v = *reinterpret_cast<const float4*>(row + 4);
                row += SROW;
                const __nv_bfloat162* p0 = reinterpret_cast<const __nv_bfloat162*>(&u);
                const __nv_bfloat162* p1 = reinterpret_cast<const __nv_bfloat162*>(&v);
                #pragma unroll
                for (int c = 0; c < 4; c++) {
                    float2 f0 = __bfloat1622float2(p0[c]);
                    float2 f1 = __bfloat1622float2(p1[c]);
                    o[2 * c]     += a * f0.x;
                    o[2 * c + 1] += a * f0.y;
                    o[8 + 2 * c]     += a * f1.x;
                    o[8 + 2 * c + 1] += a * f1.y;
                }
            }
        }
    }

    float* Og = Og0 + chanBase + poff;
    #pragma unroll
    for (int c = 0; c < 16; c++)
        Og[(long)(half * 16 + c) * HW] = o[c];
}

// ---------------- LayerNorm 1: planar (B,C3,HW) -> row-major (N,C3) ----------------
__global__ __launch_bounds__(256)
void ln1_kernel(const float* __restrict__ T1, float* __restrict__ X,
                const float* __restrict__ g, const float* __restrict__ bta)
{
    __shared__ float s[C3][33];
    const int tid = threadIdx.x;
    const long base = (long)blockIdx.x * 32;
    const int b  = (int)(base / HW);
    const int n0 = (int)(base % HW);
    const float* Tb = T1 + (long)b * C3 * HW + n0;

    for (int i = tid; i < C3 * 32; i += 256) {
        int c = i >> 5, l = i & 31;
        s[c][l] = Tb[(long)c * HW + l];
    }
    __syncthreads();

    const int warp = tid >> 5, lane = tid & 31;
    for (int p = warp * 4; p < warp * 4 + 4; p++) {
        float sum = 0.f, sq = 0.f;
        #pragma unroll
        for (int k = 0; k < 8; k++) {
            float v = s[lane + 32 * k][p];
            sum += v; sq += v * v;
        }
        #pragma unroll
        for (int o = 16; o > 0; o >>= 1) {
            sum += __shfl_xor_sync(0xffffffffu, sum, o);
            sq  += __shfl_xor_sync(0xffffffffu, sq,  o);
        }
        float mu   = sum * (1.f / C3);
        float var  = sq * (1.f / C3) - mu * mu;
        float rstd = rsqrtf(var + LNEPS);
        float* Xr = X + (base + p) * (long)C3;
        #pragma unroll
        for (int k = 0; k < 8; k++) {
            int c = lane + 32 * k;
            Xr[c] = (s[c][p] - mu) * rstd * g[c] + bta[c];
        }
    }
}

// ---------------- LayerNorm 2: row-major (N,C3) -> planar (B,C3,HW) ----------------
__global__ __launch_bounds__(256)
void ln2_kernel(const float* __restrict__ Z, float* __restrict__ Out,
                const float* __restrict__ g, const float* __restrict__ bta)
{
    __shared__ float s[C3][33];
    const int tid = threadIdx.x;
    const long base = (long)blockIdx.x * 32;
    const int b  = (int)(base / HW);
    const int n0 = (int)(base % HW);

    for (int i = tid; i < 32 * C3; i += 256) {
        int p = i >> 8, c = i & 255;
        s[c][p] = Z[(base + p) * (long)C3 + c];
    }
    __syncthreads();

    const int warp = tid >> 5, lane = tid & 31;
    for (int p = warp * 4; p < warp * 4 + 4; p++) {
        float sum = 0.f, sq = 0.f;
        #pragma unroll
        for (int k = 0; k < 8; k++) {
            float v = s[lane + 32 * k][p];
            sum += v; sq += v * v;
        }
        #pragma unroll
        for (int o = 16; o > 0; o >>= 1) {
            sum += __shfl_xor_sync(0xffffffffu, sum, o);
            sq  += __shfl_xor_sync(0xffffffffu, sq,  o);
        }
        float mu   = sum * (1.f / C3);
        float var  = sq * (1.f / C3) - mu * mu;
        float rstd = rsqrtf(var + LNEPS);
        #pragma unroll
        for (int k = 0; k < 8; k++) {
            int c = lane + 32 * k;
            s[c][p] = (s[c][p] - mu) * rstd * g[c] + bta[c];
        }
    }
    __syncthreads();

    float* Ob = Out + (long)b * C3 * HW + n0;
    for (int i = tid; i < C3 * 32; i += 256) {
        int c = i >> 5, l = i & 31;
        Ob[(long)c * HW + l] = s[c][l];
    }
}

// ---------------- launch ----------------
extern "C" void kernel_launch(void* const* d_in, const int* in_sizes, int n_in,
                              void* d_out, int out_size)
{
    const float* F_lidar = (const float*)d_in[0];
    const float* F_cam   = (const float*)d_in[1];
    const float* Wq  = (const float*)d_in[2];
    const float* Wk  = (const float*)d_in[3];
    const float* Wv  = (const float*)d_in[4];
    const float* Wo  = (const float*)d_in[5];
    const float* Wr  = (const float*)d_in[6];
    const float* g1  = (const float*)d_in[7];
    const float* b1  = (const float*)d_in[8];
    const float* g2  = (const float*)d_in[9];
    const float* b2  = (const float*)d_in[10];
    const float* W1  = (const float*)d_in[11];
    const float* bf1 = (const float*)d_in[12];
    const float* W2  = (const float*)d_in[13];
    const float* bf2 = (const float*)d_in[14];
    float* out = (float*)d_out;

    float *Qb, *Kb, *Vb, *AOb, *T1b, *Xb, *Yb, *Zb;
    cudaGetSymbolAddress((void**)&Qb,  g_Q);
    cudaGetSymbolAddress((void**)&Kb,  g_K);
    cudaGetSymbolAddress((void**)&Vb,  g_V);
    cudaGetSymbolAddress((void**)&AOb, g_AO);
    cudaGetSymbolAddress((void**)&T1b, g_T1);
    cudaGetSymbolAddress((void**)&Xb,  g_X);
    cudaGetSymbolAddress((void**)&Yb,  g_Y);
    cudaGetSymbolAddress((void**)&Zb,  g_Z);

    const dim3 gridProj((HW + BN - 1) / BN, C3 / BM, BB);   // (313, 2, 2)

    tgemm_kernel<false, false, false, false><<<gridProj, 256>>>(
        Wq, F_lidar, Qb, nullptr, nullptr,
        C3, HW, C1, C1, HW, HW, (long)C1 * HW, (long)C3 * HW);
    tgemm_kernel<false, false, false, false><<<gridProj, 256>>>(
        Wk, F_cam, Kb, nullptr, nullptr,
        C3, HW, C2, C2, HW, HW, (long)C2 * HW, (long)C3 * HW);
    tgemm_kernel<false, false, false, false><<<gridProj, 256>>>(
        Wv, F_cam, Vb, nullptr, nullptr,
        C3, HW, C2, C2, HW, HW, (long)C2 * HW, (long)C3 * HW);

    attn_kernel<<<dim3(WW2 / 8, HH / 8, BB * HEADS), 128>>>(Qb, Kb, Vb, AOb);

    tgemm_kernel<false, false, false, false><<<gridProj, 256>>>(
        Wo, AOb, T1b, nullptr, nullptr,
        C3, HW, C3, C3, HW, HW, (long)C3 * HW, (long)C3 * HW);
    tgemm_kernel<true, false, false, false><<<gridProj, 256>>>(
        Wr, F_lidar, T1b, nullptr, nullptr,
        C3, HW, C1, C1, HW, HW, (long)C1 * HW, (long)C3 * HW);

    ln1_kernel<<<NPIX / 32, 256>>>(T1b, Xb, g1, b1);

    tgemm_kernel<false, true, true, false><<<dim3(CF / BN, NPIX / BM, 1), 256>>>(
        Xb, W1, Yb, bf1, nullptr,
        NPIX, CF, C3, C3, CF, CF, 0, 0);

    tgemm_kernel<false, true, false, true><<<dim3(C3 / BN, NPIX / BM, 1), 256>>>(
        Yb, W2, Zb, bf2, Xb,
        NPIX, C3, CF, CF, C3, C3, 0, 0);

    ln2_kernel<<<NPIX / 32, 256>>>(Zb, out, g2, b2);
}

// round 4
// speedup vs baseline: 2.5584x; 1.0235x over previous
#include <cuda_runtime.h>
#include <cuda_bf16.h>
#include <math.h>
#include <stdint.h>

// ---------------- problem constants ----------------
#define BB    2
#define C1    64
#define C2    256
#define C3    256
#define HH    200
#define WW2   200
#define HW    40000        // HH*WW2
#define NPIX  80000        // BB*HW
#define HEADS 8
#define HD    32           // C3/HEADS
#define WS    7
#define PADW  3
#define CF    1024         // 4*C3
#define SCALE 0.17677669529663689f   // HD^-0.5
#define LNEPS 1e-5f

// ---------------- scratch (device globals; no runtime allocation) ----------------
__device__ float g_Q [(long)BB*C3*HW];
__device__ float g_K [(long)BB*C3*HW];
__device__ float g_V [(long)BB*C3*HW];
__device__ float g_AO[(long)BB*C3*HW];
__device__ float g_T1[(long)BB*C3*HW];
__device__ float g_X [(long)NPIX*C3];
__device__ float g_Y [(long)NPIX*CF];
__device__ float g_Z [(long)NPIX*C3];

// ---------------- tf32 helpers ----------------
__device__ __forceinline__ float to_tf32(float x) {
    uint32_t u;
    asm("cvt.rna.tf32.f32 %0, %1;" : "=r"(u) : "f"(x));
    return __uint_as_float(u);
}

__device__ __forceinline__ void mma_tf32(float* c, const uint32_t* a, const uint32_t* b) {
    asm volatile(
        "mma.sync.aligned.m16n8k8.row.col.f32.tf32.tf32.f32 "
        "{%0,%1,%2,%3},{%4,%5,%6,%7},{%8,%9},{%0,%1,%2,%3};"
        : "+f"(c[0]), "+f"(c[1]), "+f"(c[2]), "+f"(c[3])
        : "r"(a[0]), "r"(a[1]), "r"(a[2]), "r"(a[3]), "r"(b[0]), "r"(b[1]));
}

// ---------------- bf16 mma helpers ----------------
__device__ __forceinline__ void mma_bf16(float* c, const uint32_t* a, const uint32_t* b) {
    asm volatile(
        "mma.sync.aligned.m16n8k16.row.col.f32.bf16.bf16.f32 "
        "{%0,%1,%2,%3},{%4,%5,%6,%7},{%8,%9},{%0,%1,%2,%3};"
        : "+f"(c[0]), "+f"(c[1]), "+f"(c[2]), "+f"(c[3])
        : "r"(a[0]), "r"(a[1]), "r"(a[2]), "r"(a[3]), "r"(b[0]), "r"(b[1]));
}

__device__ __forceinline__ void ldsm4(uint32_t& r0, uint32_t& r1, uint32_t& r2, uint32_t& r3,
                                      uint32_t addr) {
    asm volatile("ldmatrix.sync.aligned.m8n8.x4.shared.b16 {%0,%1,%2,%3},[%4];"
                 : "=r"(r0), "=r"(r1), "=r"(r2), "=r"(r3) : "r"(addr));
}

__device__ __forceinline__ void ldsm4t(uint32_t& r0, uint32_t& r1, uint32_t& r2, uint32_t& r3,
                                       uint32_t addr) {
    asm volatile("ldmatrix.sync.aligned.m8n8.x4.trans.shared.b16 {%0,%1,%2,%3},[%4];"
                 : "=r"(r0), "=r"(r1), "=r"(r2), "=r"(r3) : "r"(addr));
}

__device__ __forceinline__ uint32_t saddr(const void* p) {
    return (uint32_t)__cvta_generic_to_shared(p);
}

__device__ __forceinline__ uint32_t packbf2(float a, float b) {
    __nv_bfloat162 t = __floats2bfloat162_rn(a, b);  // .x = a (lo), .y = b (hi)
    return *reinterpret_cast<uint32_t*>(&t);
}

// ---------------- tensor-core GEMM (tf32 mma.sync) ----------------
#define BM 128
#define BN 128
#define BKT 16

template<bool ACCUM, bool BIAS, bool RELU, bool RESID>
__global__ __launch_bounds__(256, 2)
void tgemm_kernel(const float* __restrict__ A, const float* __restrict__ B,
                  float* __restrict__ C, const float* __restrict__ bias,
                  const float* __restrict__ Res,
                  int M, int N, int K, int lda, int ldb, int ldc,
                  long strideB, long strideC)
{
    B += (long)blockIdx.z * strideB;
    C += (long)blockIdx.z * strideC;
    const float* ResB = RESID ? (Res + (long)blockIdx.z * strideC) : nullptr;

    __shared__ float As[2][BM][BKT + 4];
    __shared__ float Bs[2][BKT][BN + 8];

    const int tid  = threadIdx.x;
    const int lane = tid & 31;
    const int warp = tid >> 5;
    const int warpM = (warp >> 2) * 64;
    const int warpN = (warp & 3) * 32;
    const int lr = lane >> 2;
    const int lc = lane & 3;

    const int rowBase = blockIdx.y * BM;
    const int colBase = blockIdx.x * BN;

    const int aR  = tid >> 2;
    const int aK4 = (tid & 3) * 4;
    const int bK  = tid >> 5;
    const int bC4 = (tid & 31) * 4;

    float acc[4][4][4];
    #pragma unroll
    for (int i = 0; i < 4; i++)
        #pragma unroll
        for (int j = 0; j < 4; j++)
            #pragma unroll
            for (int e = 0; e < 4; e++) acc[i][j][e] = 0.f;

    const int numT = K / BKT;
    float4 pa[2], pb[2];

    {
        #pragma unroll
        for (int u = 0; u < 2; u++) {
            int r = rowBase + aR + 64 * u;
            pa[u] = (r < M) ? *reinterpret_cast<const float4*>(&A[(long)r * lda + aK4])
                            : make_float4(0.f, 0.f, 0.f, 0.f);
            int c = colBase + bC4;
            pb[u] = (c < N) ? *reinterpret_cast<const float4*>(&B[(long)(bK + 8 * u) * ldb + c])
                            : make_float4(0.f, 0.f, 0.f, 0.f);
        }
        #pragma unroll
        for (int u = 0; u < 2; u++) {
            As[0][aR + 64 * u][aK4 + 0] = to_tf32(pa[u].x);
            As[0][aR + 64 * u][aK4 + 1] = to_tf32(pa[u].y);
            As[0][aR + 64 * u][aK4 + 2] = to_tf32(pa[u].z);
            As[0][aR + 64 * u][aK4 + 3] = to_tf32(pa[u].w);
            Bs[0][bK + 8 * u][bC4 + 0] = to_tf32(pb[u].x);
            Bs[0][bK + 8 * u][bC4 + 1] = to_tf32(pb[u].y);
            Bs[0][bK + 8 * u][bC4 + 2] = to_tf32(pb[u].z);
            Bs[0][bK + 8 * u][bC4 + 3] = to_tf32(pb[u].w);
        }
    }
    __syncthreads();

    for (int t = 0; t < numT; t++) {
        const int cur = t & 1, nxt = cur ^ 1;
        const int k0n = (t + 1) * BKT;

        if (t + 1 < numT) {
            #pragma unroll
            for (int u = 0; u < 2; u++) {
                int r = rowBase + aR + 64 * u;
                pa[u] = (r < M) ? *reinterpret_cast<const float4*>(&A[(long)r * lda + k0n + aK4])
                                : make_float4(0.f, 0.f, 0.f, 0.f);
                int c = colBase + bC4;
                pb[u] = (c < N) ? *reinterpret_cast<const float4*>(&B[(long)(k0n + bK + 8 * u) * ldb + c])
                                : make_float4(0.f, 0.f, 0.f, 0.f);
            }
        }

        #pragma unroll
        for (int kk = 0; kk < BKT; kk += 8) {
            uint32_t af[4][4], bf[4][2];
            #pragma unroll
            for (int ti = 0; ti < 4; ti++) {
                int m = warpM + 16 * ti;
                af[ti][0] = __float_as_uint(As[cur][m + lr    ][kk + lc    ]);
                af[ti][1] = __float_as_uint(As[cur][m + lr + 8][kk + lc    ]);
                af[ti][2] = __float_as_uint(As[cur][m + lr    ][kk + lc + 4]);
                af[ti][3] = __float_as_uint(As[cur][m + lr + 8][kk + lc + 4]);
            }
            #pragma unroll
            for (int tj = 0; tj < 4; tj++) {
                int n = warpN + 8 * tj;
                bf[tj][0] = __float_as_uint(Bs[cur][kk + lc    ][n + lr]);
                bf[tj][1] = __float_as_uint(Bs[cur][kk + lc + 4][n + lr]);
            }
            #pragma unroll
            for (int ti = 0; ti < 4; ti++)
                #pragma unroll
                for (int tj = 0; tj < 4; tj++)
                    mma_tf32(acc[ti][tj], af[ti], bf[tj]);
        }

        if (t + 1 < numT) {
            #pragma unroll
            for (int u = 0; u < 2; u++) {
                As[nxt][aR + 64 * u][aK4 + 0] = to_tf32(pa[u].x);
                As[nxt][aR + 64 * u][aK4 + 1] = to_tf32(pa[u].y);
                As[nxt][aR + 64 * u][aK4 + 2] = to_tf32(pa[u].z);
                As[nxt][aR + 64 * u][aK4 + 3] = to_tf32(pa[u].w);
                Bs[nxt][bK + 8 * u][bC4 + 0] = to_tf32(pb[u].x);
                Bs[nxt][bK + 8 * u][bC4 + 1] = to_tf32(pb[u].y);
                Bs[nxt][bK + 8 * u][bC4 + 2] = to_tf32(pb[u].z);
                Bs[nxt][bK + 8 * u][bC4 + 3] = to_tf32(pb[u].w);
            }
        }
        __syncthreads();
    }

    #pragma unroll
    for (int ti = 0; ti < 4; ti++) {
        #pragma unroll
        for (int h = 0; h < 2; h++) {
            int r = rowBase + warpM + 16 * ti + lr + 8 * h;
            if (r >= M) continue;
            #pragma unroll
            for (int tj = 0; tj < 4; tj++) {
                int c = colBase + warpN + 8 * tj + 2 * lc;
                if (c >= N) continue;
                long idx = (long)r * ldc + c;
                float v0 = acc[ti][tj][2 * h + 0];
                float v1 = acc[ti][tj][2 * h + 1];
                if (BIAS)  { v0 += bias[c]; v1 += bias[c + 1]; }
                if (RESID) { float2 rr = *reinterpret_cast<const float2*>(&ResB[idx]);
                             v0 += rr.x; v1 += rr.y; }
                if (ACCUM) { float2 cc = *reinterpret_cast<const float2*>(&C[idx]);
                             v0 += cc.x; v1 += cc.y; }
                if (RELU)  { v0 = fmaxf(v0, 0.f); v1 = fmaxf(v1, 0.f); }
                *reinterpret_cast<float2*>(&C[idx]) = make_float2(v0, v1);
            }
        }
    }
}

// ---------------- local-window attention: tensor-core flash style ----------------
// Block: 128 threads (4 warps), 8x8 pixel tile, 14x14 halo (196 key pixels,
// padded to 208). S = Q(64x32) Khalo^T via bf16 mma, masked online softmax,
// O = P Vhalo via bf16 mma. Warp w owns query rows 16w..16w+15 (ty = 2w, 2w+1)
// and only visits key-chunks covering kp in [28w, 28w+111].
#define NKP 208
#define KR  40          // bf16 halves per smem row (32 data + 8 pad); 80B: LDSM conflict-free

__global__ __launch_bounds__(128, 4)
void attn_kernel(const float* __restrict__ Qg0, const float* __restrict__ Kg0,
                 const float* __restrict__ Vg0, float* __restrict__ Og0)
{
    __shared__ __align__(16) __nv_bfloat16 sK[NKP * KR];
    __shared__ __align__(16) __nv_bfloat16 sV[NKP * KR];
    __shared__ __align__(16) __nv_bfloat16 sQ[64 * KR];

    const int tid  = threadIdx.x;
    const int lane = tid & 31;
    const int warp = tid >> 5;

    const int b  = blockIdx.z >> 3;
    const int hd = blockIdx.z & 7;
    const int h0 = blockIdx.y * 8, w0 = blockIdx.x * 8;

    const long chanBase = ((long)b * C3 + hd * HD) * HW;
    const float* Kg = Kg0 + chanBase;
    const float* Vg = Vg0 + chanBase;
    const float* Qg = Qg0 + chanBase;

    // ---- fill K/V halo (196 rows x 32 ch, bf16) ----
    for (int i = tid; i < 196 * 16; i += 128) {
        int p = i >> 4, cp = i & 15;
        int ph = h0 - PADW + p / 14;
        int pw = w0 - PADW + p % 14;
        ph = ph < 0 ? 0 : (ph > HH - 1 ? HH - 1 : ph);
        pw = pw < 0 ? 0 : (pw > WW2 - 1 ? WW2 - 1 : pw);
        long off = (long)(2 * cp) * HW + ph * WW2 + pw;
        *reinterpret_cast<__nv_bfloat162*>(&sK[p * KR + 2 * cp]) =
            __floats2bfloat162_rn(Kg[off], Kg[off + HW]);
        *reinterpret_cast<__nv_bfloat162*>(&sV[p * KR + 2 * cp]) =
            __floats2bfloat162_rn(Vg[off], Vg[off + HW]);
    }
    // zero pad rows (so P=0 x V never makes NaN)
    for (int i = tid; i < 12 * 16; i += 128) {
        int p = 196 + (i >> 4), cp = i & 15;
        __nv_bfloat162 z = __floats2bfloat162_rn(0.f, 0.f);
        *reinterpret_cast<__nv_bfloat162*>(&sK[p * KR + 2 * cp]) = z;
        *reinterpret_cast<__nv_bfloat162*>(&sV[p * KR + 2 * cp]) = z;
    }
    // ---- fill Q (64 rows x 32 ch) ----
    for (int i = tid; i < 64 * 16; i += 128) {
        int p = i >> 4, cp = i & 15;
        long off = (long)(2 * cp) * HW + (long)(h0 + (p >> 3)) * WW2 + (w0 + (p & 7));
        *reinterpret_cast<__nv_bfloat162*>(&sQ[p * KR + 2 * cp]) =
            __floats2bfloat162_rn(Qg[off], Qg[off + HW]);
    }
    __syncthreads();

    const int lr = lane >> 2, lc = lane & 3;
    const int ty0 = 2 * warp;      // row lr has ty = 2w; row lr+8 has ty = 2w+1
    const int tx  = lr;            // (16w + lr) & 7 == lr

    // Q a-frags (k=0..15 and k=16..31)
    uint32_t aq0[4], aq1[4];
    {
        int qrow = 16 * warp + (lane & 15);
        int qcol = (lane >> 4) * 8;
        ldsm4(aq0[0], aq0[1], aq0[2], aq0[3], saddr(&sQ[qrow * KR + qcol]));
        ldsm4(aq1[0], aq1[1], aq1[2], aq1[3], saddr(&sQ[qrow * KR + 16 + qcol]));
    }

    float m20 = -60.f, m21 = -60.f;    // running max (base-2 logit domain)
    float l0 = 0.f, l1 = 0.f;          // running sum (per-lane partial over lc)
    float acco[4][4];
    #pragma unroll
    for (int i = 0; i < 4; i++)
        #pragma unroll
        for (int j = 0; j < 4; j++) acco[i][j] = 0.f;

    const float LSC = SCALE * 1.4426950408889634f;   // scale * log2(e)
    const int c0 = (28 * warp) >> 4;
    const int c1 = (28 * warp + 111) >> 4;

    for (int c = c0; c <= c1; c++) {
        const int n0 = c * 16;

        // ---- S = Q K^T for this 16-col chunk (2 n-tiles) ----
        float s0[4] = {0.f, 0.f, 0.f, 0.f};
        float s1[4] = {0.f, 0.f, 0.f, 0.f};
        {
            const int krow = n0 + (lane & 7) + ((lane >> 3) & 1) * 8;
            const int kcol = (lane >> 4) * 8;
            uint32_t r0, r1, r2, r3;
            ldsm4(r0, r1, r2, r3, saddr(&sK[krow * KR + kcol]));
            { uint32_t f[2] = {r0, r2}; mma_bf16(s0, aq0, f); }
            { uint32_t f[2] = {r1, r3}; mma_bf16(s1, aq0, f); }
            ldsm4(r0, r1, r2, r3, saddr(&sK[krow * KR + 16 + kcol]));
            { uint32_t f[2] = {r0, r2}; mma_bf16(s0, aq1, f); }
            { uint32_t f[2] = {r1, r3}; mma_bf16(s1, aq1, f); }
        }

        // ---- mask + online softmax update ----
        float pv0[4], pv1[4];
        float cm0 = -1e30f, cm1 = -1e30f;
        #pragma unroll
        for (int u = 0; u < 4; u++) {
            const int t = u >> 1, j = u & 1;
            const int col = n0 + 8 * t + 2 * lc + j;
            const int hy = (col * 2341) >> 15;         // col / 14 (col < 208)
            const int hx = col - 14 * hy;
            const int dy = hy - ty0;
            const bool okx = (unsigned)(hx - tx) <= 6u;
            const float v0 = (t ? s1[j]     : s0[j])     * LSC;
            const float v1 = (t ? s1[j + 2] : s0[j + 2]) * LSC;
            const float e0 = (okx && (unsigned)dy       <= 6u) ? v0 : -1e30f;
            const float e1 = (okx && (unsigned)(dy - 1) <= 6u) ? v1 : -1e30f;
            pv0[u] = e0; pv1[u] = e1;
            cm0 = fmaxf(cm0, e0); cm1 = fmaxf(cm1, e1);
        }
        cm0 = fmaxf(cm0, __shfl_xor_sync(0xffffffffu, cm0, 1));
        cm0 = fmaxf(cm0, __shfl_xor_sync(0xffffffffu, cm0, 2));
        cm1 = fmaxf(cm1, __shfl_xor_sync(0xffffffffu, cm1, 1));
        cm1 = fmaxf(cm1, __shfl_xor_sync(0xffffffffu, cm1, 2));

        const float mn0 = fmaxf(m20, cm0), mn1 = fmaxf(m21, cm1);
        const float fs0 = exp2f(m20 - mn0), fs1 = exp2f(m21 - mn1);
        m20 = mn0; m21 = mn1;

        #pragma unroll
        for (int u = 0; u < 4; u++) {
            pv0[u] = exp2f(pv0[u] - mn0);
            pv1[u] = exp2f(pv1[u] - mn1);
        }
        l0 = l0 * fs0 + pv0[0] + pv0[1] + pv0[2] + pv0[3];
        l1 = l1 * fs1 + pv1[0] + pv1[1] + pv1[2] + pv1[3];

        #pragma unroll
        for (int vt = 0; vt < 4; vt++) {
            acco[vt][0] *= fs0; acco[vt][1] *= fs0;
            acco[vt][2] *= fs1; acco[vt][3] *= fs1;
        }

        // ---- P (c-frag == a-frag identity) ----
        uint32_t pa[4];
        pa[0] = packbf2(pv0[0], pv0[1]);
        pa[1] = packbf2(pv1[0], pv1[1]);
        pa[2] = packbf2(pv0[2], pv0[3]);
        pa[3] = packbf2(pv1[2], pv1[3]);

        // ---- O += P V for this chunk (4 V n-tiles of 8 channels) ----
        {
            const int vrow = n0 + (lane & 7) + ((lane >> 3) & 1) * 8;
            const int vcol = (lane >> 4) * 8;
            uint32_t r0, r1, r2, r3;
            ldsm4t(r0, r1, r2, r3, saddr(&sV[vrow * KR + vcol]));
            { uint32_t f[2] = {r0, r1}; mma_bf16(acco[0], pa, f); }
            { uint32_t f[2] = {r2, r3}; mma_bf16(acco[1], pa, f); }
            ldsm4t(r0, r1, r2, r3, saddr(&sV[vrow * KR + 16 + vcol]));
            { uint32_t f[2] = {r0, r1}; mma_bf16(acco[2], pa, f); }
            { uint32_t f[2] = {r2, r3}; mma_bf16(acco[3], pa, f); }
        }
    }

    // ---- finalize: normalize and store (planar layout) ----
    l0 += __shfl_xor_sync(0xffffffffu, l0, 1);
    l0 += __shfl_xor_sync(0xffffffffu, l0, 2);
    l1 += __shfl_xor_sync(0xffffffffu, l1, 1);
    l1 += __shfl_xor_sync(0xffffffffu, l1, 2);
    const float inv0 = 1.f / l0, inv1 = 1.f / l1;

    const int pr = 16 * warp + lr;
    const long po0 = (long)(h0 + (pr >> 3)) * WW2 + (w0 + lr);
    const long po1 = po0 + WW2;
    float* Ob = Og0 + chanBase;
    #pragma unroll
    for (int vt = 0; vt < 4; vt++) {
        #pragma unroll
        for (int j = 0; j < 2; j++) {
            const int ch = 8 * vt + 2 * lc + j;
            Ob[(long)ch * HW + po0] = acco[vt][j]     * inv0;
            Ob[(long)ch * HW + po1] = acco[vt][2 + j] * inv1;
        }
    }
}

// ---------------- LayerNorm 1: planar (B,C3,HW) -> row-major (N,C3) ----------------
__global__ __launch_bounds__(256)
void ln1_kernel(const float* __restrict__ T1, float* __restrict__ X,
                const float* __restrict__ g, const float* __restrict__ bta)
{
    __shared__ float s[C3][33];
    const int tid = threadIdx.x;
    const long base = (long)blockIdx.x * 32;
    const int b  = (int)(base / HW);
    const int n0 = (int)(base % HW);
    const float* Tb = T1 + (long)b * C3 * HW + n0;

    for (int i = tid; i < C3 * 32; i += 256) {
        int c = i >> 5, l = i & 31;
        s[c][l] = Tb[(long)c * HW + l];
    }
    __syncthreads();

    const int warp = tid >> 5, lane = tid & 31;
    for (int p = warp * 4; p < warp * 4 + 4; p++) {
        float sum = 0.f, sq = 0.f;
        #pragma unroll
        for (int k = 0; k < 8; k++) {
            float v = s[lane + 32 * k][p];
            sum += v; sq += v * v;
        }
        #pragma unroll
        for (int o = 16; o > 0; o >>= 1) {
            sum += __shfl_xor_sync(0xffffffffu, sum, o);
            sq  += __shfl_xor_sync(0xffffffffu, sq,  o);
        }
        float mu   = sum * (1.f / C3);
        float var  = sq * (1.f / C3) - mu * mu;
        float rstd = rsqrtf(var + LNEPS);
        float* Xr = X + (base + p) * (long)C3;
        #pragma unroll
        for (int k = 0; k < 8; k++) {
            int c = lane + 32 * k;
            Xr[c] = (s[c][p] - mu) * rstd * g[c] + bta[c];
        }
    }
}

// ---------------- LayerNorm 2: row-major (N,C3) -> planar (B,C3,HW) ----------------
__global__ __launch_bounds__(256)
void ln2_kernel(const float* __restrict__ Z, float* __restrict__ Out,
                const float* __restrict__ g, const float* __restrict__ bta)
{
    __shared__ float s[C3][33];
    const int tid = threadIdx.x;
    const long base = (long)blockIdx.x * 32;
    const int b  = (int)(base / HW);
    const int n0 = (int)(base % HW);

    for (int i = tid; i < 32 * C3; i += 256) {
        int p = i >> 8, c = i & 255;
        s[c][p] = Z[(base + p) * (long)C3 + c];
    }
    __syncthreads();

    const int warp = tid >> 5, lane = tid & 31;
    for (int p = warp * 4; p < warp * 4 + 4; p++) {
        float sum = 0.f, sq = 0.f;
        #pragma unroll
        for (int k = 0; k < 8; k++) {
            float v = s[lane + 32 * k][p];
            sum += v; sq += v * v;
        }
        #pragma unroll
        for (int o = 16; o > 0; o >>= 1) {
            sum += __shfl_xor_sync(0xffffffffu, sum, o);
            sq  += __shfl_xor_sync(0xffffffffu, sq,  o);
        }
        float mu   = sum * (1.f / C3);
        float var  = sq * (1.f / C3) - mu * mu;
        float rstd = rsqrtf(var + LNEPS);
        #pragma unroll
        for (int k = 0; k < 8; k++) {
            int c = lane + 32 * k;
            s[c][p] = (s[c][p] - mu) * rstd * g[c] + bta[c];
        }
    }
    __syncthreads();

    float* Ob = Out + (long)b * C3 * HW + n0;
    for (int i = tid; i < C3 * 32; i += 256) {
        int c = i >> 5, l = i & 31;
        Ob[(long)c * HW + l] = s[c][l];
    }
}

// ---------------- launch ----------------
extern "C" void kernel_launch(void* const* d_in, const int* in_sizes, int n_in,
                              void* d_out, int out_size)
{
    const float* F_lidar = (const float*)d_in[0];
    const float* F_cam   = (const float*)d_in[1];
    const float* Wq  = (const float*)d_in[2];
    const float* Wk  = (const float*)d_in[3];
    const float* Wv  = (const float*)d_in[4];
    const float* Wo  = (const float*)d_in[5];
    const float* Wr  = (const float*)d_in[6];
    const float* g1  = (const float*)d_in[7];
    const float* b1  = (const float*)d_in[8];
    const float* g2  = (const float*)d_in[9];
    const float* b2  = (const float*)d_in[10];
    const float* W1  = (const float*)d_in[11];
    const float* bf1 = (const float*)d_in[12];
    const float* W2  = (const float*)d_in[13];
    const float* bf2 = (const float*)d_in[14];
    float* out = (float*)d_out;

    float *Qb, *Kb, *Vb, *AOb, *T1b, *Xb, *Yb, *Zb;
    cudaGetSymbolAddress((void**)&Qb,  g_Q);
    cudaGetSymbolAddress((void**)&Kb,  g_K);
    cudaGetSymbolAddress((void**)&Vb,  g_V);
    cudaGetSymbolAddress((void**)&AOb, g_AO);
    cudaGetSymbolAddress((void**)&T1b, g_T1);
    cudaGetSymbolAddress((void**)&Xb,  g_X);
    cudaGetSymbolAddress((void**)&Yb,  g_Y);
    cudaGetSymbolAddress((void**)&Zb,  g_Z);

    const dim3 gridProj((HW + BN - 1) / BN, C3 / BM, BB);   // (313, 2, 2)

    tgemm_kernel<false, false, false, false><<<gridProj, 256>>>(
        Wq, F_lidar, Qb, nullptr, nullptr,
        C3, HW, C1, C1, HW, HW, (long)C1 * HW, (long)C3 * HW);
    tgemm_kernel<false, false, false, false><<<gridProj, 256>>>(
        Wk, F_cam, Kb, nullptr, nullptr,
        C3, HW, C2, C2, HW, HW, (long)C2 * HW, (long)C3 * HW);
    tgemm_kernel<false, false, false, false><<<gridProj, 256>>>(
        Wv, F_cam, Vb, nullptr, nullptr,
        C3, HW, C2, C2, HW, HW, (long)C2 * HW, (long)C3 * HW);

    attn_kernel<<<dim3(WW2 / 8, HH / 8, BB * HEADS), 128>>>(Qb, Kb, Vb, AOb);

    tgemm_kernel<false, false, false, false><<<gridProj, 256>>>(
        Wo, AOb, T1b, nullptr, nullptr,
        C3, HW, C3, C3, HW, HW, (long)C3 * HW, (long)C3 * HW);
    tgemm_kernel<true, false, false, false><<<gridProj, 256>>>(
        Wr, F_lidar, T1b, nullptr, nullptr,
        C3, HW, C1, C1, HW, HW, (long)C1 * HW, (long)C3 * HW);

    ln1_kernel<<<NPIX / 32, 256>>>(T1b, Xb, g1, b1);

    tgemm_kernel<false, true, true, false><<<dim3(CF / BN, NPIX / BM, 1), 256>>>(
        Xb, W1, Yb, bf1, nullptr,
        NPIX, CF, C3, C3, CF, CF, 0, 0);

    tgemm_kernel<false, true, false, true><<<dim3(C3 / BN, NPIX / BM, 1), 256>>>(
        Yb, W2, Zb, bf2, Xb,
        NPIX, C3, CF, CF, C3, C3, 0, 0);

    ln2_kernel<<<NPIX / 32, 256>>>(Zb, out, g2, b2);
}

// round 6
// speedup vs baseline: 2.9697x; 1.1608x over previous
#include <cuda_runtime.h>
#include <cuda_bf16.h>
#include <math.h>
#include <stdint.h>

// ---------------- problem constants ----------------
#define BB    2
#define C1    64
#define C2    256
#define C3    256
#define HH    200
#define WW2   200
#define HW    40000        // HH*WW2
#define NPIX  80000        // BB*HW
#define HEADS 8
#define HD    32           // C3/HEADS
#define WS    7
#define PADW  3
#define CF    1024         // 4*C3
#define SCALE 0.17677669529663689f   // HD^-0.5
#define LNEPS 1e-5f

// ---------------- scratch (device globals; no runtime allocation) ----------------
__device__ __nv_bfloat16 g_Qt[(long)NPIX*C3];   // pixel-major bf16 Q
__device__ __nv_bfloat16 g_Kt[(long)NPIX*C3];
__device__ __nv_bfloat16 g_Vt[(long)NPIX*C3];
__device__ float g_AO[(long)BB*C3*HW];
__device__ float g_T1[(long)BB*C3*HW];
__device__ float g_X [(long)NPIX*C3];
__device__ float g_Y [(long)NPIX*CF];
__device__ float g_Z [(long)NPIX*C3];

// ---------------- tf32 helpers ----------------
__device__ __forceinline__ float to_tf32(float x) {
    uint32_t u;
    asm("cvt.rna.tf32.f32 %0, %1;" : "=r"(u) : "f"(x));
    return __uint_as_float(u);
}

__device__ __forceinline__ void mma_tf32(float* c, const uint32_t* a, const uint32_t* b) {
    asm volatile(
        "mma.sync.aligned.m16n8k8.row.col.f32.tf32.tf32.f32 "
        "{%0,%1,%2,%3},{%4,%5,%6,%7},{%8,%9},{%0,%1,%2,%3};"
        : "+f"(c[0]), "+f"(c[1]), "+f"(c[2]), "+f"(c[3])
        : "r"(a[0]), "r"(a[1]), "r"(a[2]), "r"(a[3]), "r"(b[0]), "r"(b[1]));
}

// ---------------- bf16 mma helpers ----------------
__device__ __forceinline__ void mma_bf16(float* c, const uint32_t* a, const uint32_t* b) {
    asm volatile(
        "mma.sync.aligned.m16n8k16.row.col.f32.bf16.bf16.f32 "
        "{%0,%1,%2,%3},{%4,%5,%6,%7},{%8,%9},{%0,%1,%2,%3};"
        : "+f"(c[0]), "+f"(c[1]), "+f"(c[2]), "+f"(c[3])
        : "r"(a[0]), "r"(a[1]), "r"(a[2]), "r"(a[3]), "r"(b[0]), "r"(b[1]));
}

__device__ __forceinline__ void ldsm4(uint32_t& r0, uint32_t& r1, uint32_t& r2, uint32_t& r3,
                                      uint32_t addr) {
    asm volatile("ldmatrix.sync.aligned.m8n8.x4.shared.b16 {%0,%1,%2,%3},[%4];"
                 : "=r"(r0), "=r"(r1), "=r"(r2), "=r"(r3) : "r"(addr));
}

__device__ __forceinline__ void ldsm4t(uint32_t& r0, uint32_t& r1, uint32_t& r2, uint32_t& r3,
                                       uint32_t addr) {
    asm volatile("ldmatrix.sync.aligned.m8n8.x4.trans.shared.b16 {%0,%1,%2,%3},[%4];"
                 : "=r"(r0), "=r"(r1), "=r"(r2), "=r"(r3) : "r"(addr));
}

__device__ __forceinline__ uint32_t saddr(const void* p) {
    return (uint32_t)__cvta_generic_to_shared(p);
}

__device__ __forceinline__ uint32_t packbf2(float a, float b) {
    __nv_bfloat162 t = __floats2bfloat162_rn(a, b);
    return *reinterpret_cast<uint32_t*>(&t);
}

// ---------------- tensor-core GEMM (tf32 mma.sync) ----------------
// Normal mode: C fp32 row-major [+accum][+bias][+res][relu].
// BF16T mode: writes bf16 TRANSPOSED pixel-major: Cbf[col*ldc + row].
#define BM 128
#define BN 128
#define BKT 16

template<bool ACCUM, bool BIAS, bool RELU, bool RESID, bool BF16T>
__global__ __launch_bounds__(256, 2)
void tgemm_kernel(const float* __restrict__ A, const float* __restrict__ B,
                  float* __restrict__ C, __nv_bfloat16* __restrict__ Cbf,
                  const float* __restrict__ bias, const float* __restrict__ Res,
                  int M, int N, int K, int lda, int ldb, int ldc,
                  long strideB, long strideC)
{
    B += (long)blockIdx.z * strideB;
    if (BF16T) Cbf += (long)blockIdx.z * strideC;
    else       C   += (long)blockIdx.z * strideC;
    const float* ResB = RESID ? (Res + (long)blockIdx.z * strideC) : nullptr;

    __shared__ float As[2][BM][BKT + 4];
    __shared__ float Bs[2][BKT][BN + 8];

    const int tid  = threadIdx.x;
    const int lane = tid & 31;
    const int warp = tid >> 5;
    const int warpM = (warp >> 2) * 64;
    const int warpN = (warp & 3) * 32;
    const int lr = lane >> 2;
    const int lc = lane & 3;

    const int rowBase = blockIdx.y * BM;
    const int colBase = blockIdx.x * BN;

    const int aR  = tid >> 2;
    const int aK4 = (tid & 3) * 4;
    const int bK  = tid >> 5;
    const int bC4 = (tid & 31) * 4;

    float acc[4][4][4];
    #pragma unroll
    for (int i = 0; i < 4; i++)
        #pragma unroll
        for (int j = 0; j < 4; j++)
            #pragma unroll
            for (int e = 0; e < 4; e++) acc[i][j][e] = 0.f;

    const int numT = K / BKT;
    float4 pa[2], pb[2];

    {
        #pragma unroll
        for (int u = 0; u < 2; u++) {
            int r = rowBase + aR + 64 * u;
            pa[u] = (r < M) ? *reinterpret_cast<const float4*>(&A[(long)r * lda + aK4])
                            : make_float4(0.f, 0.f, 0.f, 0.f);
            int c = colBase + bC4;
            pb[u] = (c < N) ? *reinterpret_cast<const float4*>(&B[(long)(bK + 8 * u) * ldb + c])
                            : make_float4(0.f, 0.f, 0.f, 0.f);
        }
        #pragma unroll
        for (int u = 0; u < 2; u++) {
            As[0][aR + 64 * u][aK4 + 0] = to_tf32(pa[u].x);
            As[0][aR + 64 * u][aK4 + 1] = to_tf32(pa[u].y);
            As[0][aR + 64 * u][aK4 + 2] = to_tf32(pa[u].z);
            As[0][aR + 64 * u][aK4 + 3] = to_tf32(pa[u].w);
            Bs[0][bK + 8 * u][bC4 + 0] = to_tf32(pb[u].x);
            Bs[0][bK + 8 * u][bC4 + 1] = to_tf32(pb[u].y);
            Bs[0][bK + 8 * u][bC4 + 2] = to_tf32(pb[u].z);
            Bs[0][bK + 8 * u][bC4 + 3] = to_tf32(pb[u].w);
        }
    }
    __syncthreads();

    for (int t = 0; t < numT; t++) {
        const int cur = t & 1, nxt = cur ^ 1;
        const int k0n = (t + 1) * BKT;

        if (t + 1 < numT) {
            #pragma unroll
            for (int u = 0; u < 2; u++) {
                int r = rowBase + aR + 64 * u;
                pa[u] = (r < M) ? *reinterpret_cast<const float4*>(&A[(long)r * lda + k0n + aK4])
                                : make_float4(0.f, 0.f, 0.f, 0.f);
                int c = colBase + bC4;
                pb[u] = (c < N) ? *reinterpret_cast<const float4*>(&B[(long)(k0n + bK + 8 * u) * ldb + c])
                                : make_float4(0.f, 0.f, 0.f, 0.f);
            }
        }

        #pragma unroll
        for (int kk = 0; kk < BKT; kk += 8) {
            uint32_t af[4][4], bf[4][2];
            #pragma unroll
            for (int ti = 0; ti < 4; ti++) {
                int m = warpM + 16 * ti;
                af[ti][0] = __float_as_uint(As[cur][m + lr    ][kk + lc    ]);
                af[ti][1] = __float_as_uint(As[cur][m + lr + 8][kk + lc    ]);
                af[ti][2] = __float_as_uint(As[cur][m + lr    ][kk + lc + 4]);
                af[ti][3] = __float_as_uint(As[cur][m + lr + 8][kk + lc + 4]);
            }
            #pragma unroll
            for (int tj = 0; tj < 4; tj++) {
                int n = warpN + 8 * tj;
                bf[tj][0] = __float_as_uint(Bs[cur][kk + lc    ][n + lr]);
                bf[tj][1] = __float_as_uint(Bs[cur][kk + lc + 4][n + lr]);
            }
            #pragma unroll
            for (int ti = 0; ti < 4; ti++)
                #pragma unroll
                for (int tj = 0; tj < 4; tj++)
                    mma_tf32(acc[ti][tj], af[ti], bf[tj]);
        }

        if (t + 1 < numT) {
            #pragma unroll
            for (int u = 0; u < 2; u++) {
                As[nxt][aR + 64 * u][aK4 + 0] = to_tf32(pa[u].x);
                As[nxt][aR + 64 * u][aK4 + 1] = to_tf32(pa[u].y);
                As[nxt][aR + 64 * u][aK4 + 2] = to_tf32(pa[u].z);
                As[nxt][aR + 64 * u][aK4 + 3] = to_tf32(pa[u].w);
                Bs[nxt][bK + 8 * u][bC4 + 0] = to_tf32(pb[u].x);
                Bs[nxt][bK + 8 * u][bC4 + 1] = to_tf32(pb[u].y);
                Bs[nxt][bK + 8 * u][bC4 + 2] = to_tf32(pb[u].z);
                Bs[nxt][bK + 8 * u][bC4 + 3] = to_tf32(pb[u].w);
            }
        }
        __syncthreads();
    }

    #pragma unroll
    for (int ti = 0; ti < 4; ti++) {
        #pragma unroll
        for (int h = 0; h < 2; h++) {
            int r = rowBase + warpM + 16 * ti + lr + 8 * h;
            if (r >= M) continue;
            #pragma unroll
            for (int tj = 0; tj < 4; tj++) {
                int c = colBase + warpN + 8 * tj + 2 * lc;
                if (c >= N) continue;
                float v0 = acc[ti][tj][2 * h + 0];
                float v1 = acc[ti][tj][2 * h + 1];
                if (BF16T) {
                    // transposed pixel-major bf16 store: Cbf[col*ldc + row]
                    Cbf[(long)c * ldc + r]       = __float2bfloat16(v0);
                    Cbf[(long)(c + 1) * ldc + r] = __float2bfloat16(v1);
                } else {
                    long idx = (long)r * ldc + c;
                    if (BIAS)  { v0 += bias[c]; v1 += bias[c + 1]; }
                    if (RESID) { float2 rr = *reinterpret_cast<const float2*>(&ResB[idx]);
                                 v0 += rr.x; v1 += rr.y; }
                    if (ACCUM) { float2 cc = *reinterpret_cast<const float2*>(&C[idx]);
                                 v0 += cc.x; v1 += cc.y; }
                    if (RELU)  { v0 = fmaxf(v0, 0.f); v1 = fmaxf(v1, 0.f); }
                    *reinterpret_cast<float2*>(&C[idx]) = make_float2(v0, v1);
                }
            }
        }
    }
}

// ---------------- local-window attention: tensor-core flash style ----------------
// Q/K/V come in bf16 pixel-major [b][pix][256]; head hd owns cols hd*32..+31.
// Halo fill = pure uint4 copies (64 B per pixel, 4 threads each).
#define NKP 208
#define KR  40          // bf16 halves per smem row (32 data + 8 pad), 80 B: LDSM conflict-free

__global__ __launch_bounds__(128, 5)
void attn_kernel(const __nv_bfloat16* __restrict__ Qt, const __nv_bfloat16* __restrict__ Kt,
                 const __nv_bfloat16* __restrict__ Vt, float* __restrict__ Og0)
{
    __shared__ __align__(16) __nv_bfloat16 sK[NKP * KR];
    __shared__ __align__(16) __nv_bfloat16 sV[NKP * KR];
    __shared__ __align__(16) __nv_bfloat16 sQ[64 * KR];

    const int tid  = threadIdx.x;
    const int lane = tid & 31;
    const int warp = tid >> 5;

    const int b  = blockIdx.z >> 3;
    const int hd = blockIdx.z & 7;
    const int h0 = blockIdx.y * 8, w0 = blockIdx.x * 8;

    const long tBase = (long)b * HW * C3 + hd * HD;   // + pix*C3
    const __nv_bfloat16* Kb = Kt + tBase;
    const __nv_bfloat16* Vb = Vt + tBase;
    const __nv_bfloat16* Qb = Qt + tBase;

    // ---- fill K/V halo: 196 pixels x 64 B, 4 threads per pixel ----
    for (int i = tid; i < 196 * 4; i += 128) {
        const int p = i >> 2, seg = i & 3;
        int ph = h0 - PADW + p / 14;
        int pw = w0 - PADW + p % 14;
        ph = ph < 0 ? 0 : (ph > HH - 1 ? HH - 1 : ph);
        pw = pw < 0 ? 0 : (pw > WW2 - 1 ? WW2 - 1 : pw);
        const long src = (long)(ph * WW2 + pw) * C3 + seg * 8;
        *reinterpret_cast<uint4*>(&sK[p * KR + seg * 8]) =
            *reinterpret_cast<const uint4*>(Kb + src);
        *reinterpret_cast<uint4*>(&sV[p * KR + seg * 8]) =
            *reinterpret_cast<const uint4*>(Vb + src);
    }
    // zero pad rows 196..207
    for (int i = tid; i < 12 * 4; i += 128) {
        const int p = 196 + (i >> 2), seg = i & 3;
        uint4 z = make_uint4(0u, 0u, 0u, 0u);
        *reinterpret_cast<uint4*>(&sK[p * KR + seg * 8]) = z;
        *reinterpret_cast<uint4*>(&sV[p * KR + seg * 8]) = z;
    }
    // ---- fill Q: 64 pixels x 64 B ----
    for (int i = tid; i < 64 * 4; i += 128) {
        const int p = i >> 2, seg = i & 3;
        const long src = (long)((h0 + (p >> 3)) * WW2 + (w0 + (p & 7))) * C3 + seg * 8;
        *reinterpret_cast<uint4*>(&sQ[p * KR + seg * 8]) =
            *reinterpret_cast<const uint4*>(Qb + src);
    }
    __syncthreads();

    const int lr = lane >> 2, lc = lane & 3;
    const int ty0 = 2 * warp;
    const int tx  = lr;

    uint32_t aq0[4], aq1[4];
    {
        int qrow = 16 * warp + (lane & 15);
        int qcol = (lane >> 4) * 8;
        ldsm4(aq0[0], aq0[1], aq0[2], aq0[3], saddr(&sQ[qrow * KR + qcol]));
        ldsm4(aq1[0], aq1[1], aq1[2], aq1[3], saddr(&sQ[qrow * KR + 16 + qcol]));
    }

    float m20 = -60.f, m21 = -60.f;
    float l0 = 0.f, l1 = 0.f;
    float acco[4][4];
    #pragma unroll
    for (int i = 0; i < 4; i++)
        #pragma unroll
        for (int j = 0; j < 4; j++) acco[i][j] = 0.f;

    const float LSC = SCALE * 1.4426950408889634f;
    const int c0 = (28 * warp) >> 4;
    const int c1 = (28 * warp + 111) >> 4;

    for (int c = c0; c <= c1; c++) {
        const int n0 = c * 16;

        float s0[4] = {0.f, 0.f, 0.f, 0.f};
        float s1[4] = {0.f, 0.f, 0.f, 0.f};
        {
            const int krow = n0 + (lane & 7) + ((lane >> 3) & 1) * 8;
            const int kcol = (lane >> 4) * 8;
            uint32_t r0, r1, r2, r3;
            ldsm4(r0, r1, r2, r3, saddr(&sK[krow * KR + kcol]));
            { uint32_t f[2] = {r0, r2}; mma_bf16(s0, aq0, f); }
            { uint32_t f[2] = {r1, r3}; mma_bf16(s1, aq0, f); }
            ldsm4(r0, r1, r2, r3, saddr(&sK[krow * KR + 16 + kcol]));
            { uint32_t f[2] = {r0, r2}; mma_bf16(s0, aq1, f); }
            { uint32_t f[2] = {r1, r3}; mma_bf16(s1, aq1, f); }
        }

        float pv0[4], pv1[4];
        float cm0 = -1e30f, cm1 = -1e30f;
        #pragma unroll
        for (int u = 0; u < 4; u++) {
            const int t = u >> 1, j = u & 1;
            const int col = n0 + 8 * t + 2 * lc + j;
            const int hy = (col * 2341) >> 15;
            const int hx = col - 14 * hy;
            const int dy = hy - ty0;
            const bool okx = (unsigned)(hx - tx) <= 6u;
            const float v0 = (t ? s1[j]     : s0[j])     * LSC;
            const float v1 = (t ? s1[j + 2] : s0[j + 2]) * LSC;
            const float e0 = (okx && (unsigned)dy       <= 6u) ? v0 : -1e30f;
            const float e1 = (okx && (unsigned)(dy - 1) <= 6u) ? v1 : -1e30f;
            pv0[u] = e0; pv1[u] = e1;
            cm0 = fmaxf(cm0, e0); cm1 = fmaxf(cm1, e1);
        }
        cm0 = fmaxf(cm0, __shfl_xor_sync(0xffffffffu, cm0, 1));
        cm0 = fmaxf(cm0, __shfl_xor_sync(0xffffffffu, cm0, 2));
        cm1 = fmaxf(cm1, __shfl_xor_sync(0xffffffffu, cm1, 1));
        cm1 = fmaxf(cm1, __shfl_xor_sync(0xffffffffu, cm1, 2));

        const float mn0 = fmaxf(m20, cm0), mn1 = fmaxf(m21, cm1);
        const float fs0 = exp2f(m20 - mn0), fs1 = exp2f(m21 - mn1);
        m20 = mn0; m21 = mn1;

        #pragma unroll
        for (int u = 0; u < 4; u++) {
            pv0[u] = exp2f(pv0[u] - mn0);
            pv1[u] = exp2f(pv1[u] - mn1);
        }
        l0 = l0 * fs0 + pv0[0] + pv0[1] + pv0[2] + pv0[3];
        l1 = l1 * fs1 + pv1[0] + pv1[1] + pv1[2] + pv1[3];

        #pragma unroll
        for (int vt = 0; vt < 4; vt++) {
            acco[vt][0] *= fs0; acco[vt][1] *= fs0;
            acco[vt][2] *= fs1; acco[vt][3] *= fs1;
        }

        uint32_t pa[4];
        pa[0] = packbf2(pv0[0], pv0[1]);
        pa[1] = packbf2(pv1[0], pv1[1]);
        pa[2] = packbf2(pv0[2], pv0[3]);
        pa[3] = packbf2(pv1[2], pv1[3]);

        {
            const int vrow = n0 + (lane & 7) + ((lane >> 3) & 1) * 8;
            const int vcol = (lane >> 4) * 8;
            uint32_t r0, r1, r2, r3;
            ldsm4t(r0, r1, r2, r3, saddr(&sV[vrow * KR + vcol]));
            { uint32_t f[2] = {r0, r1}; mma_bf16(acco[0], pa, f); }
            { uint32_t f[2] = {r2, r3}; mma_bf16(acco[1], pa, f); }
            ldsm4t(r0, r1, r2, r3, saddr(&sV[vrow * KR + 16 + vcol]));
            { uint32_t f[2] = {r0, r1}; mma_bf16(acco[2], pa, f); }
            { uint32_t f[2] = {r2, r3}; mma_bf16(acco[3], pa, f); }
        }
    }

    l0 += __shfl_xor_sync(0xffffffffu, l0, 1);
    l0 += __shfl_xor_sync(0xffffffffu, l0, 2);
    l1 += __shfl_xor_sync(0xffffffffu, l1, 1);
    l1 += __shfl_xor_sync(0xffffffffu, l1, 2);
    const float inv0 = 1.f / l0, inv1 = 1.f / l1;

    const int pr = 16 * warp + lr;
    const long po0 = (long)(h0 + (pr >> 3)) * WW2 + (w0 + lr);
    const long po1 = po0 + WW2;
    float* Ob = Og0 + ((long)b * C3 + hd * HD) * HW;
    #pragma unroll
    for (int vt = 0; vt < 4; vt++) {
        #pragma unroll
        for (int j = 0; j < 2; j++) {
            const int ch = 8 * vt + 2 * lc + j;
            Ob[(long)ch * HW + po0] = acco[vt][j]     * inv0;
            Ob[(long)ch * HW + po1] = acco[vt][2 + j] * inv1;
        }
    }
}

// ---------------- LayerNorm 1: planar (B,C3,HW) -> row-major (N,C3) ----------------
__global__ __launch_bounds__(256)
void ln1_kernel(const float* __restrict__ T1, float* __restrict__ X,
                const float* __restrict__ g, const float* __restrict__ bta)
{
    __shared__ float s[C3][33];
    const int tid = threadIdx.x;
    const long base = (long)blockIdx.x * 32;
    const int b  = (int)(base / HW);
    const int n0 = (int)(base % HW);
    const float* Tb = T1 + (long)b * C3 * HW + n0;

    for (int i = tid; i < C3 * 32; i += 256) {
        int c = i >> 5, l = i & 31;
        s[c][l] = Tb[(long)c * HW + l];
    }
    __syncthreads();

    const int warp = tid >> 5, lane = tid & 31;
    for (int p = warp * 4; p < warp * 4 + 4; p++) {
        float sum = 0.f, sq = 0.f;
        #pragma unroll
        for (int k = 0; k < 8; k++) {
            float v = s[lane + 32 * k][p];
            sum += v; sq += v * v;
        }
        #pragma unroll
        for (int o = 16; o > 0; o >>= 1) {
            sum += __shfl_xor_sync(0xffffffffu, sum, o);
            sq  += __shfl_xor_sync(0xffffffffu, sq,  o);
        }
        float mu   = sum * (1.f / C3);
        float var  = sq * (1.f / C3) - mu * mu;
        float rstd = rsqrtf(var + LNEPS);
        float* Xr = X + (base + p) * (long)C3;
        #pragma unroll
        for (int k = 0; k < 8; k++) {
            int c = lane + 32 * k;
            Xr[c] = (s[c][p] - mu) * rstd * g[c] + bta[c];
        }
    }
}

// ---------------- LayerNorm 2: row-major (N,C3) -> planar (B,C3,HW) ----------------
__global__ __launch_bounds__(256)
void ln2_kernel(const float* __restrict__ Z, float* __restrict__ Out,
                const float* __restrict__ g, const float* __restrict__ bta)
{
    __shared__ float s[C3][33];
    const int tid = threadIdx.x;
    const long base = (long)blockIdx.x * 32;
    const int b  = (int)(base / HW);
    const int n0 = (int)(base % HW);

    for (int i = tid; i < 32 * C3; i += 256) {
        int p = i >> 8, c = i & 255;
        s[c][p] = Z[(base + p) * (long)C3 + c];
    }
    __syncthreads();

    const int warp = tid >> 5, lane = tid & 31;
    for (int p = warp * 4; p < warp * 4 + 4; p++) {
        float sum = 0.f, sq = 0.f;
        #pragma unroll
        for (int k = 0; k < 8; k++) {
            float v = s[lane + 32 * k][p];
            sum += v; sq += v * v;
        }
        #pragma unroll
        for (int o = 16; o > 0; o >>= 1) {
            sum += __shfl_xor_sync(0xffffffffu, sum, o);
            sq  += __shfl_xor_sync(0xffffffffu, sq,  o);
        }
        float mu   = sum * (1.f / C3);
        float var  = sq * (1.f / C3) - mu * mu;
        float rstd = rsqrtf(var + LNEPS);
        #pragma unroll
        for (int k = 0; k < 8; k++) {
            int c = lane + 32 * k;
            s[c][p] = (s[c][p] - mu) * rstd * g[c] + bta[c];
        }
    }
    __syncthreads();

    float* Ob = Out + (long)b * C3 * HW + n0;
    for (int i = tid; i < C3 * 32; i += 256) {
        int c = i >> 5, l = i & 31;
        Ob[(long)c * HW + l] = s[c][l];
    }
}

// ---------------- launch ----------------
extern "C" void kernel_launch(void* const* d_in, const int* in_sizes, int n_in,
                              void* d_out, int out_size)
{
    const float* F_lidar = (const float*)d_in[0];
    const float* F_cam   = (const float*)d_in[1];
    const float* Wq  = (const float*)d_in[2];
    const float* Wk  = (const float*)d_in[3];
    const float* Wv  = (const float*)d_in[4];
    const float* Wo  = (const float*)d_in[5];
    const float* Wr  = (const float*)d_in[6];
    const float* g1  = (const float*)d_in[7];
    const float* b1  = (const float*)d_in[8];
    const float* g2  = (const float*)d_in[9];
    const float* b2  = (const float*)d_in[10];
    const float* W1  = (const float*)d_in[11];
    const float* bf1 = (const float*)d_in[12];
    const float* W2  = (const float*)d_in[13];
    const float* bf2 = (const float*)d_in[14];
    float* out = (float*)d_out;

    __nv_bfloat16 *Qtb, *Ktb, *Vtb;
    float *AOb, *T1b, *Xb, *Yb, *Zb;
    cudaGetSymbolAddress((void**)&Qtb, g_Qt);
    cudaGetSymbolAddress((void**)&Ktb, g_Kt);
    cudaGetSymbolAddress((void**)&Vtb, g_Vt);
    cudaGetSymbolAddress((void**)&AOb, g_AO);
    cudaGetSymbolAddress((void**)&T1b, g_T1);
    cudaGetSymbolAddress((void**)&Xb,  g_X);
    cudaGetSymbolAddress((void**)&Yb,  g_Y);
    cudaGetSymbolAddress((void**)&Zb,  g_Z);

    const dim3 gridProj((HW + BN - 1) / BN, C3 / BM, BB);   // (313, 2, 2)

    // Q/K/V -> bf16 pixel-major [b][pix][256]
    tgemm_kernel<false, false, false, false, true><<<gridProj, 256>>>(
        Wq, F_lidar, nullptr, Qtb, nullptr, nullptr,
        C3, HW, C1, C1, HW, C3, (long)C1 * HW, (long)C3 * HW);
    tgemm_kernel<false, false, false, false, true><<<gridProj, 256>>>(
        Wk, F_cam, nullptr, Ktb, nullptr, nullptr,
        C3, HW, C2, C2, HW, C3, (long)C2 * HW, (long)C3 * HW);
    tgemm_kernel<false, false, false, false, true><<<gridProj, 256>>>(
        Wv, F_cam, nullptr, Vtb, nullptr, nullptr,
        C3, HW, C2, C2, HW, C3, (long)C2 * HW, (long)C3 * HW);

    attn_kernel<<<dim3(WW2 / 8, HH / 8, BB * HEADS), 128>>>(Qtb, Ktb, Vtb, AOb);

    tgemm_kernel<false, false, false, false, false><<<gridProj, 256>>>(
        Wo, AOb, T1b, nullptr, nullptr, nullptr,
        C3, HW, C3, C3, HW, HW, (long)C3 * HW, (long)C3 * HW);
    tgemm_kernel<true, false, false, false, false><<<gridProj, 256>>>(
        Wr, F_lidar, T1b, nullptr, nullptr, nullptr,
        C3, HW, C1, C1, HW, HW, (long)C1 * HW, (long)C3 * HW);

    ln1_kernel<<<NPIX / 32, 256>>>(T1b, Xb, g1, b1);

    tgemm_kernel<false, true, true, false, false><<<dim3(CF / BN, NPIX / BM, 1), 256>>>(
        Xb, W1, Yb, nullptr, bf1, nullptr,
        NPIX, CF, C3, C3, CF, CF, 0, 0);

    tgemm_kernel<false, true, false, true, false><<<dim3(C3 / BN, NPIX / BM, 1), 256>>>(
        Yb, W2, Zb, nullptr, bf2, Xb,
        NPIX, C3, CF, CF, C3, C3, 0, 0);

    ln2_kernel<<<NPIX / 32, 256>>>(Zb, out, g2, b2);
}

// round 8
// speedup vs baseline: 3.6432x; 1.2268x over previous
#include <cuda_runtime.h>
#include <cuda_bf16.h>
#include <math.h>
#include <stdint.h>

// ---------------- problem constants ----------------
#define BB    2
#define C1    64
#define C2    256
#define C3    256
#define HH    200
#define WW2   200
#define HW    40000
#define NPIX  80000
#define HEADS 8
#define HD    32
#define WS    7
#define PADW  3
#define CF    1024
#define SCALE 0.17677669529663689f
#define LNEPS 1e-5f

// ---------------- scratch (device globals; no runtime allocation) ----------------
__device__ __nv_bfloat16 g_Qt[(long)NPIX*C3];
__device__ __nv_bfloat16 g_Kt[(long)NPIX*C3];
__device__ __nv_bfloat16 g_Vt[(long)NPIX*C3];
__device__ float g_AO[(long)BB*C3*HW];
__device__ float g_T1[(long)BB*C3*HW];
__device__ float g_X [(long)NPIX*C3];
__device__ float g_Y [(long)NPIX*CF];
__device__ float g_Z [(long)NPIX*C3];

// pre-converted (tf32-rna) weights, packed: Wq|Wk|Wv|Wo|Wr|W1|W2
#define WOFF_Q  0
#define WOFF_K  16384
#define WOFF_V  81920
#define WOFF_O  147456
#define WOFF_R  212992
#define WOFF_1  229376
#define WOFF_2  491520
#define WTOT    753664
__device__ float g_Wc[WTOT];

// ---------------- helpers ----------------
__device__ __forceinline__ float to_tf32(float x) {
    uint32_t u;
    asm("cvt.rna.tf32.f32 %0, %1;" : "=r"(u) : "f"(x));
    return __uint_as_float(u);
}

__device__ __forceinline__ void mma_tf32(float* c, const uint32_t* a, const uint32_t* b) {
    asm volatile(
        "mma.sync.aligned.m16n8k8.row.col.f32.tf32.tf32.f32 "
        "{%0,%1,%2,%3},{%4,%5,%6,%7},{%8,%9},{%0,%1,%2,%3};"
        : "+f"(c[0]), "+f"(c[1]), "+f"(c[2]), "+f"(c[3])
        : "r"(a[0]), "r"(a[1]), "r"(a[2]), "r"(a[3]), "r"(b[0]), "r"(b[1]));
}

__device__ __forceinline__ void mma_bf16(float* c, const uint32_t* a, const uint32_t* b) {
    asm volatile(
        "mma.sync.aligned.m16n8k16.row.col.f32.bf16.bf16.f32 "
        "{%0,%1,%2,%3},{%4,%5,%6,%7},{%8,%9},{%0,%1,%2,%3};"
        : "+f"(c[0]), "+f"(c[1]), "+f"(c[2]), "+f"(c[3])
        : "r"(a[0]), "r"(a[1]), "r"(a[2]), "r"(a[3]), "r"(b[0]), "r"(b[1]));
}

__device__ __forceinline__ void ldsm4(uint32_t& r0, uint32_t& r1, uint32_t& r2, uint32_t& r3,
                                      uint32_t addr) {
    asm volatile("ldmatrix.sync.aligned.m8n8.x4.shared.b16 {%0,%1,%2,%3},[%4];"
                 : "=r"(r0), "=r"(r1), "=r"(r2), "=r"(r3) : "r"(addr));
}

__device__ __forceinline__ void ldsm4t(uint32_t& r0, uint32_t& r1, uint32_t& r2, uint32_t& r3,
                                       uint32_t addr) {
    asm volatile("ldmatrix.sync.aligned.m8n8.x4.trans.shared.b16 {%0,%1,%2,%3},[%4];"
                 : "=r"(r0), "=r"(r1), "=r"(r2), "=r"(r3) : "r"(addr));
}

__device__ __forceinline__ uint32_t saddr(const void* p) {
    return (uint32_t)__cvta_generic_to_shared(p);
}

__device__ __forceinline__ uint32_t packbf2(float a, float b) {
    __nv_bfloat162 t = __floats2bfloat162_rn(a, b);
    return *reinterpret_cast<uint32_t*>(&t);
}

__device__ __forceinline__ void cpa16(uint32_t dst, const void* src, int sz) {
    asm volatile("cp.async.cg.shared.global [%0], [%1], 16, %2;\n"
                 :: "r"(dst), "l"(src), "r"(sz));
}
__device__ __forceinline__ void cpa_commit() {
    asm volatile("cp.async.commit_group;\n" ::: "memory");
}
template<int N_>
__device__ __forceinline__ void cpa_wait() {
    asm volatile("cp.async.wait_group %0;\n" :: "n"(N_) : "memory");
}

// ---------------- weight pre-conversion (fp32 -> tf32-rna) ----------------
__global__ void wconv_kernel(const float* w0, const float* w1, const float* w2,
                             const float* w3, const float* w4, const float* w5,
                             const float* w6, float* dst)
{
    int i = (blockIdx.x * 256 + threadIdx.x) * 4;
    if (i >= WTOT) return;
    const float* src; int off;
    if      (i < WOFF_K) { src = w0; off = WOFF_Q; }
    else if (i < WOFF_V) { src = w1; off = WOFF_K; }
    else if (i < WOFF_O) { src = w2; off = WOFF_V; }
    else if (i < WOFF_R) { src = w3; off = WOFF_O; }
    else if (i < WOFF_1) { src = w4; off = WOFF_R; }
    else if (i < WOFF_2) { src = w5; off = WOFF_1; }
    else                 { src = w6; off = WOFF_2; }
    float4 v = *reinterpret_cast<const float4*>(src + (i - off));
    v.x = to_tf32(v.x); v.y = to_tf32(v.y); v.z = to_tf32(v.z); v.w = to_tf32(v.w);
    *reinterpret_cast<float4*>(dst + i) = v;
}

// ---------------- tensor-core GEMM: cp.async 3-stage pipeline, tf32 mma ----------------
// C[M,N] = A[M,K] * B[K,N] (+ A2[M,K2]*B2[K2,N] if DUAL) [+bias][+res][relu]
// BF16T: bf16 transposed store Cbf[col*ldc+row]; TF32OUT: rna-round fp32 output.
// Requires M%128==0 (grid covers exactly), K%16==0, N%4==0.
#define BM 128
#define BN 128
#define BKT 16
#define NSTAGE 3
#define GSMEM ((NSTAGE*BM*(BKT+4) + NSTAGE*BKT*(BN+8)) * 4)   // 56832 B

template<bool BIAS, bool RELU, bool RESID, bool BF16T, bool DUAL, bool TF32OUT>
__global__ __launch_bounds__(256, 2)
void tgemm_kernel(const float* __restrict__ A, const float* __restrict__ B,
                  const float* __restrict__ A2, const float* __restrict__ B2,
                  float* __restrict__ C, __nv_bfloat16* __restrict__ Cbf,
                  const float* __restrict__ bias, const float* __restrict__ Res,
                  int M, int N, int K, int K2,
                  int lda, int ldb, int lda2, int ldb2, int ldc,
                  long strideB, long strideB2, long strideC)
{
    extern __shared__ float dsm[];
    typedef float (*AsT)[BM][BKT + 4];
    typedef float (*BsT)[BKT][BN + 8];
    AsT As = reinterpret_cast<AsT>(dsm);
    BsT Bs = reinterpret_cast<BsT>(dsm + NSTAGE * BM * (BKT + 4));

    B += (long)blockIdx.z * strideB;
    if (DUAL) B2 += (long)blockIdx.z * strideB2;
    if (BF16T) Cbf += (long)blockIdx.z * strideC;
    else       C   += (long)blockIdx.z * strideC;
    const float* ResB = RESID ? (Res + (long)blockIdx.z * strideC) : nullptr;

    const int tid  = threadIdx.x;
    const int lane = tid & 31;
    const int warp = tid >> 5;
    const int warpM = (warp >> 2) * 64;
    const int warpN = (warp & 3) * 32;
    const int lr = lane >> 2;
    const int lc = lane & 3;

    const int rowBase = blockIdx.y * BM;
    const int colBase = blockIdx.x * BN;

    const int aR  = tid >> 2;           // 0..63 (+64)
    const int aK4 = (tid & 3) * 4;
    const int bK  = tid >> 5;           // 0..7 (+8)
    const int bC4 = (tid & 31) * 4;
    const int bOk = (colBase + bC4 < N) ? 16 : 0;

    float acc[4][4][4];
    #pragma unroll
    for (int i = 0; i < 4; i++)
        #pragma unroll
        for (int j = 0; j < 4; j++)
            #pragma unroll
            for (int e = 0; e < 4; e++) acc[i][j][e] = 0.f;

    #pragma unroll
    for (int ph = 0; ph < (DUAL ? 2 : 1); ph++) {
        const float* Ap  = ph ? A2  : A;
        const float* Bp  = ph ? B2  : B;
        const int Kp     = ph ? K2  : K;
        const int ldap   = ph ? lda2 : lda;
        const int ldbp   = ph ? ldb2 : ldb;
        const int numT   = Kp / BKT;

        if (DUAL && ph) __syncthreads();   // protect smem reuse across phases

        // prologue: issue tiles 0 .. NSTAGE-2
        #pragma unroll
        for (int t = 0; t < NSTAGE - 1; t++) {
            if (t < numT) {
                const int k0 = t * BKT;
                #pragma unroll
                for (int u = 0; u < 2; u++)
                    cpa16(saddr(&As[t][aR + 64 * u][aK4]),
                          &Ap[(long)(rowBase + aR + 64 * u) * ldap + k0 + aK4], 16);
                #pragma unroll
                for (int u = 0; u < 2; u++)
                    cpa16(saddr(&Bs[t][bK + 8 * u][bC4]),
                          &Bp[(long)(k0 + bK + 8 * u) * ldbp + colBase + bC4], bOk);
            }
            cpa_commit();
        }

        for (int t = 0; t < numT; t++) {
            cpa_wait<NSTAGE - 2>();
            __syncthreads();

            // issue tile t + NSTAGE-1
            {
                const int tn = t + NSTAGE - 1;
                if (tn < numT) {
                    const int k0 = tn * BKT;
                    const int st = tn % NSTAGE;
                    #pragma unroll
                    for (int u = 0; u < 2; u++)
                        cpa16(saddr(&As[st][aR + 64 * u][aK4]),
                              &Ap[(long)(rowBase + aR + 64 * u) * ldap + k0 + aK4], 16);
                    #pragma unroll
                    for (int u = 0; u < 2; u++)
                        cpa16(saddr(&Bs[st][bK + 8 * u][bC4]),
                              &Bp[(long)(k0 + bK + 8 * u) * ldbp + colBase + bC4], bOk);
                }
                cpa_commit();
            }

            // compute stage t % NSTAGE (raw fp32 bits -> HW tf32 truncation)
            const int cur = t % NSTAGE;
            #pragma unroll
            for (int kk = 0; kk < BKT; kk += 8) {
                uint32_t af[4][4], bf[4][2];
                #pragma unroll
                for (int ti = 0; ti < 4; ti++) {
                    int m = warpM + 16 * ti;
                    af[ti][0] = __float_as_uint(As[cur][m + lr    ][kk + lc    ]);
                    af[ti][1] = __float_as_uint(As[cur][m + lr + 8][kk + lc    ]);
                    af[ti][2] = __float_as_uint(As[cur][m + lr    ][kk + lc + 4]);
                    af[ti][3] = __float_as_uint(As[cur][m + lr + 8][kk + lc + 4]);
                }
                #pragma unroll
                for (int tj = 0; tj < 4; tj++) {
                    int n = warpN + 8 * tj;
                    bf[tj][0] = __float_as_uint(Bs[cur][kk + lc    ][n + lr]);
                    bf[tj][1] = __float_as_uint(Bs[cur][kk + lc + 4][n + lr]);
                }
                #pragma unroll
                for (int ti = 0; ti < 4; ti++)
                    #pragma unroll
                    for (int tj = 0; tj < 4; tj++)
                        mma_tf32(acc[ti][tj], af[ti], bf[tj]);
            }
        }
    }

    // ---- epilogue ----
    #pragma unroll
    for (int ti = 0; ti < 4; ti++) {
        #pragma unroll
        for (int h = 0; h < 2; h++) {
            int r = rowBase + warpM + 16 * ti + lr + 8 * h;
            #pragma unroll
            for (int tj = 0; tj < 4; tj++) {
                int c = colBase + warpN + 8 * tj + 2 * lc;
                if (c >= N) continue;
                float v0 = acc[ti][tj][2 * h + 0];
                float v1 = acc[ti][tj][2 * h + 1];
                if (BF16T) {
                    Cbf[(long)c * ldc + r]       = __float2bfloat16(v0);
                    Cbf[(long)(c + 1) * ldc + r] = __float2bfloat16(v1);
                } else {
                    long idx = (long)r * ldc + c;
                    if (BIAS)  { v0 += bias[c]; v1 += bias[c + 1]; }
                    if (RESID) { float2 rr = *reinterpret_cast<const float2*>(&ResB[idx]);
                                 v0 += rr.x; v1 += rr.y; }
                    if (RELU)  { v0 = fmaxf(v0, 0.f); v1 = fmaxf(v1, 0.f); }
                    if (TF32OUT) { v0 = to_tf32(v0); v1 = to_tf32(v1); }
                    *reinterpret_cast<float2*>(&C[idx]) = make_float2(v0, v1);
                }
            }
        }
    }
}

// ---------------- local-window attention: tensor-core flash style ----------------
#define NKP 208
#define KR  40

__global__ __launch_bounds__(128, 5)
void attn_kernel(const __nv_bfloat16* __restrict__ Qt, const __nv_bfloat16* __restrict__ Kt,
                 const __nv_bfloat16* __restrict__ Vt, float* __restrict__ Og0)
{
    __shared__ __align__(16) __nv_bfloat16 sK[NKP * KR];
    __shared__ __align__(16) __nv_bfloat16 sV[NKP * KR];
    __shared__ __align__(16) __nv_bfloat16 sQ[64 * KR];

    const int tid  = threadIdx.x;
    const int lane = tid & 31;
    const int warp = tid >> 5;

    const int b  = blockIdx.z >> 3;
    const int hd = blockIdx.z & 7;
    const int h0 = blockIdx.y * 8, w0 = blockIdx.x * 8;

    const long tBase = (long)b * HW * C3 + hd * HD;
    const __nv_bfloat16* Kb = Kt + tBase;
    const __nv_bfloat16* Vb = Vt + tBase;
    const __nv_bfloat16* Qb = Qt + tBase;

    for (int i = tid; i < 196 * 4; i += 128) {
        const int p = i >> 2, seg = i & 3;
        int ph = h0 - PADW + p / 14;
        int pw = w0 - PADW + p % 14;
        ph = ph < 0 ? 0 : (ph > HH - 1 ? HH - 1 : ph);
        pw = pw < 0 ? 0 : (pw > WW2 - 1 ? WW2 - 1 : pw);
        const long src = (long)(ph * WW2 + pw) * C3 + seg * 8;
        *reinterpret_cast<uint4*>(&sK[p * KR + seg * 8]) =
            *reinterpret_cast<const uint4*>(Kb + src);
        *reinterpret_cast<uint4*>(&sV[p * KR + seg * 8]) =
            *reinterpret_cast<const uint4*>(Vb + src);
    }
    for (int i = tid; i < 12 * 4; i += 128) {
        const int p = 196 + (i >> 2), seg = i & 3;
        uint4 z = make_uint4(0u, 0u, 0u, 0u);
        *reinterpret_cast<uint4*>(&sK[p * KR + seg * 8]) = z;
        *reinterpret_cast<uint4*>(&sV[p * KR + seg * 8]) = z;
    }
    for (int i = tid; i < 64 * 4; i += 128) {
        const int p = i >> 2, seg = i & 3;
        const long src = (long)((h0 + (p >> 3)) * WW2 + (w0 + (p & 7))) * C3 + seg * 8;
        *reinterpret_cast<uint4*>(&sQ[p * KR + seg * 8]) =
            *reinterpret_cast<const uint4*>(Qb + src);
    }
    __syncthreads();

    const int lr = lane >> 2, lc = lane & 3;
    const int ty0 = 2 * warp;
    const int tx  = lr;

    uint32_t aq0[4], aq1[4];
    {
        int qrow = 16 * warp + (lane & 15);
        int qcol = (lane >> 4) * 8;
        ldsm4(aq0[0], aq0[1], aq0[2], aq0[3], saddr(&sQ[qrow * KR + qcol]));
        ldsm4(aq1[0], aq1[1], aq1[2], aq1[3], saddr(&sQ[qrow * KR + 16 + qcol]));
    }

    float m20 = -60.f, m21 = -60.f;
    float l0 = 0.f, l1 = 0.f;
    float acco[4][4];
    #pragma unroll
    for (int i = 0; i < 4; i++)
        #pragma unroll
        for (int j = 0; j < 4; j++) acco[i][j] = 0.f;

    const float LSC = SCALE * 1.4426950408889634f;
    const int c0 = (28 * warp) >> 4;
    const int c1 = (28 * warp + 111) >> 4;

    for (int c = c0; c <= c1; c++) {
        const int n0 = c * 16;

        float s0[4] = {0.f, 0.f, 0.f, 0.f};
        float s1[4] = {0.f, 0.f, 0.f, 0.f};
        {
            const int krow = n0 + (lane & 7) + ((lane >> 3) & 1) * 8;
            const int kcol = (lane >> 4) * 8;
            uint32_t r0, r1, r2, r3;
            ldsm4(r0, r1, r2, r3, saddr(&sK[krow * KR + kcol]));
            { uint32_t f[2] = {r0, r2}; mma_bf16(s0, aq0, f); }
            { uint32_t f[2] = {r1, r3}; mma_bf16(s1, aq0, f); }
            ldsm4(r0, r1, r2, r3, saddr(&sK[krow * KR + 16 + kcol]));
            { uint32_t f[2] = {r0, r2}; mma_bf16(s0, aq1, f); }
            { uint32_t f[2] = {r1, r3}; mma_bf16(s1, aq1, f); }
        }

        float pv0[4], pv1[4];
        float cm0 = -1e30f, cm1 = -1e30f;
        #pragma unroll
        for (int u = 0; u < 4; u++) {
            const int t = u >> 1, j = u & 1;
            const int col = n0 + 8 * t + 2 * lc + j;
            const int hy = (col * 2341) >> 15;
            const int hx = col - 14 * hy;
            const int dy = hy - ty0;
            const bool okx = (unsigned)(hx - tx) <= 6u;
            const float v0 = (t ? s1[j]     : s0[j])     * LSC;
            const float v1 = (t ? s1[j + 2] : s0[j + 2]) * LSC;
            const float e0 = (okx && (unsigned)dy       <= 6u) ? v0 : -1e30f;
            const float e1 = (okx && (unsigned)(dy - 1) <= 6u) ? v1 : -1e30f;
            pv0[u] = e0; pv1[u] = e1;
            cm0 = fmaxf(cm0, e0); cm1 = fmaxf(cm1, e1);
        }
        cm0 = fmaxf(cm0, __shfl_xor_sync(0xffffffffu, cm0, 1));
        cm0 = fmaxf(cm0, __shfl_xor_sync(0xffffffffu, cm0, 2));
        cm1 = fmaxf(cm1, __shfl_xor_sync(0xffffffffu, cm1, 1));
        cm1 = fmaxf(cm1, __shfl_xor_sync(0xffffffffu, cm1, 2));

        const float mn0 = fmaxf(m20, cm0), mn1 = fmaxf(m21, cm1);
        const float fs0 = exp2f(m20 - mn0), fs1 = exp2f(m21 - mn1);
        m20 = mn0; m21 = mn1;

        #pragma unroll
        for (int u = 0; u < 4; u++) {
            pv0[u] = exp2f(pv0[u] - mn0);
            pv1[u] = exp2f(pv1[u] - mn1);
        }
        l0 = l0 * fs0 + pv0[0] + pv0[1] + pv0[2] + pv0[3];
        l1 = l1 * fs1 + pv1[0] + pv1[1] + pv1[2] + pv1[3];

        #pragma unroll
        for (int vt = 0; vt < 4; vt++) {
            acco[vt][0] *= fs0; acco[vt][1] *= fs0;
            acco[vt][2] *= fs1; acco[vt][3] *= fs1;
        }

        uint32_t pa[4];
        pa[0] = packbf2(pv0[0], pv0[1]);
        pa[1] = packbf2(pv1[0], pv1[1]);
        pa[2] = packbf2(pv0[2], pv0[3]);
        pa[3] = packbf2(pv1[2], pv1[3]);

        {
            const int vrow = n0 + (lane & 7) + ((lane >> 3) & 1) * 8;
            const int vcol = (lane >> 4) * 8;
            uint32_t r0, r1, r2, r3;
            ldsm4t(r0, r1, r2, r3, saddr(&sV[vrow * KR + vcol]));
            { uint32_t f[2] = {r0, r1}; mma_bf16(acco[0], pa, f); }
            { uint32_t f[2] = {r2, r3}; mma_bf16(acco[1], pa, f); }
            ldsm4t(r0, r1, r2, r3, saddr(&sV[vrow * KR + 16 + vcol]));
            { uint32_t f[2] = {r0, r1}; mma_bf16(acco[2], pa, f); }
            { uint32_t f[2] = {r2, r3}; mma_bf16(acco[3], pa, f); }
        }
    }

    l0 += __shfl_xor_sync(0xffffffffu, l0, 1);
    l0 += __shfl_xor_sync(0xffffffffu, l0, 2);
    l1 += __shfl_xor_sync(0xffffffffu, l1, 1);
    l1 += __shfl_xor_sync(0xffffffffu, l1, 2);
    const float inv0 = 1.f / l0, inv1 = 1.f / l1;

    const int pr = 16 * warp + lr;
    const long po0 = (long)(h0 + (pr >> 3)) * WW2 + (w0 + lr);
    const long po1 = po0 + WW2;
    float* Ob = Og0 + ((long)b * C3 + hd * HD) * HW;
    #pragma unroll
    for (int vt = 0; vt < 4; vt++) {
        #pragma unroll
        for (int j = 0; j < 2; j++) {
            const int ch = 8 * vt + 2 * lc + j;
            // rna-round: AO's only consumer is the Wo GEMM (tf32 operand)
            Ob[(long)ch * HW + po0] = to_tf32(acco[vt][j]     * inv0);
            Ob[(long)ch * HW + po1] = to_tf32(acco[vt][2 + j] * inv1);
        }
    }
}

// ---------------- LayerNorm 1: planar (B,C3,HW) -> row-major (N,C3) ----------------
__global__ __launch_bounds__(256)
void ln1_kernel(const float* __restrict__ T1, float* __restrict__ X,
                const float* __restrict__ g, const float* __restrict__ bta)
{
    __shared__ float s[C3][33];
    const int tid = threadIdx.x;
    const long base = (long)blockIdx.x * 32;
    const int b  = (int)(base / HW);
    const int n0 = (int)(base % HW);
    const float* Tb = T1 + (long)b * C3 * HW + n0;

    for (int i = tid; i < C3 * 32; i += 256) {
        int c = i >> 5, l = i & 31;
        s[c][l] = Tb[(long)c * HW + l];
    }
    __syncthreads();

    const int warp = tid >> 5, lane = tid & 31;
    for (int p = warp * 4; p < warp * 4 + 4; p++) {
        float sum = 0.f, sq = 0.f;
        #pragma unroll
        for (int k = 0; k < 8; k++) {
            float v = s[lane + 32 * k][p];
            sum += v; sq += v * v;
        }
        #pragma unroll
        for (int o = 16; o > 0; o >>= 1) {
            sum += __shfl_xor_sync(0xffffffffu, sum, o);
            sq  += __shfl_xor_sync(0xffffffffu, sq,  o);
        }
        float mu   = sum * (1.f / C3);
        float var  = sq * (1.f / C3) - mu * mu;
        float rstd = rsqrtf(var + LNEPS);
        float* Xr = X + (base + p) * (long)C3;
        #pragma unroll
        for (int k = 0; k < 8; k++) {
            int c = lane + 32 * k;
            Xr[c] = (s[c][p] - mu) * rstd * g[c] + bta[c];
        }
    }
}

// ---------------- LayerNorm 2: row-major (N,C3) -> planar (B,C3,HW) ----------------
__global__ __launch_bounds__(256)
void ln2_kernel(const float* __restrict__ Z, float* __restrict__ Out,
                const float* __restrict__ g, const float* __restrict__ bta)
{
    __shared__ float s[C3][33];
    const int tid = threadIdx.x;
    const long base = (long)blockIdx.x * 32;
    const int b  = (int)(base / HW);
    const int n0 = (int)(base % HW);

    for (int i = tid; i < 32 * C3; i += 256) {
        int p = i >> 8, c = i & 255;
        s[c][p] = Z[(base + p) * (long)C3 + c];
    }
    __syncthreads();

    const int warp = tid >> 5, lane = tid & 31;
    for (int p = warp * 4; p < warp * 4 + 4; p++) {
        float sum = 0.f, sq = 0.f;
        #pragma unroll
        for (int k = 0; k < 8; k++) {
            float v = s[lane + 32 * k][p];
            sum += v; sq += v * v;
        }
        #pragma unroll
        for (int o = 16; o > 0; o >>= 1) {
            sum += __shfl_xor_sync(0xffffffffu, sum, o);
            sq  += __shfl_xor_sync(0xffffffffu, sq,  o);
        }
        float mu   = sum * (1.f / C3);
        float var  = sq * (1.f / C3) - mu * mu;
        float rstd = rsqrtf(var + LNEPS);
        #pragma unroll
        for (int k = 0; k < 8; k++) {
            int c = lane + 32 * k;
            s[c][p] = (s[c][p] - mu) * rstd * g[c] + bta[c];
        }
    }
    __syncthreads();

    float* Ob = Out + (long)b * C3 * HW + n0;
    for (int i = tid; i < C3 * 32; i += 256) {
        int c = i >> 5, l = i & 31;
        Ob[(long)c * HW + l] = s[c][l];
    }
}

// ---------------- launch ----------------
extern "C" void kernel_launch(void* const* d_in, const int* in_sizes, int n_in,
                              void* d_out, int out_size)
{
    const float* F_lidar = (const float*)d_in[0];
    const float* F_cam   = (const float*)d_in[1];
    const float* Wq  = (const float*)d_in[2];
    const float* Wk  = (const float*)d_in[3];
    const float* Wv  = (const float*)d_in[4];
    const float* Wo  = (const float*)d_in[5];
    const float* Wr  = (const float*)d_in[6];
    const float* g1  = (const float*)d_in[7];
    const float* b1  = (const float*)d_in[8];
    const float* g2  = (const float*)d_in[9];
    const float* b2  = (const float*)d_in[10];
    const float* W1  = (const float*)d_in[11];
    const float* bf1 = (const float*)d_in[12];
    const float* W2  = (const float*)d_in[13];
    const float* bf2 = (const float*)d_in[14];
    float* out = (float*)d_out;

    __nv_bfloat16 *Qtb, *Ktb, *Vtb;
    float *AOb, *T1b, *Xb, *Yb, *Zb, *Wc;
    cudaGetSymbolAddress((void**)&Qtb, g_Qt);
    cudaGetSymbolAddress((void**)&Ktb, g_Kt);
    cudaGetSymbolAddress((void**)&Vtb, g_Vt);
    cudaGetSymbolAddress((void**)&AOb, g_AO);
    cudaGetSymbolAddress((void**)&T1b, g_T1);
    cudaGetSymbolAddress((void**)&Xb,  g_X);
    cudaGetSymbolAddress((void**)&Yb,  g_Y);
    cudaGetSymbolAddress((void**)&Zb,  g_Z);
    cudaGetSymbolAddress((void**)&Wc,  g_Wc);

    // raise dynamic smem limits for the instantiations we use
    cudaFuncSetAttribute((const void*)tgemm_kernel<false,false,false,true, false,false>,
                         cudaFuncAttributeMaxDynamicSharedMemorySize, GSMEM);
    cudaFuncSetAttribute((const void*)tgemm_kernel<false,false,false,false,true, false>,
                         cudaFuncAttributeMaxDynamicSharedMemorySize, GSMEM);
    cudaFuncSetAttribute((const void*)tgemm_kernel<true, true, false,false,false,true >,
                         cudaFuncAttributeMaxDynamicSharedMemorySize, GSMEM);
    cudaFuncSetAttribute((const void*)tgemm_kernel<true, false,true, false,false,false>,
                         cudaFuncAttributeMaxDynamicSharedMemorySize, GSMEM);

    // pre-convert weights to tf32-rna
    wconv_kernel<<<(WTOT / 4 + 255) / 256, 256>>>(Wq, Wk, Wv, Wo, Wr, W1, W2, Wc);

    const dim3 gridProj((HW + BN - 1) / BN, C3 / BM, BB);   // (313, 2, 2)

    // Q/K/V -> bf16 pixel-major
    tgemm_kernel<false,false,false,true,false,false><<<gridProj, 256, GSMEM>>>(
        Wc + WOFF_Q, F_lidar, nullptr, nullptr, nullptr, Qtb, nullptr, nullptr,
        C3, HW, C1, 0, C1, HW, 0, 0, C3, (long)C1 * HW, 0, (long)C3 * HW);
    tgemm_kernel<false,false,false,true,false,false><<<gridProj, 256, GSMEM>>>(
        Wc + WOFF_K, F_cam, nullptr, nullptr, nullptr, Ktb, nullptr, nullptr,
        C3, HW, C2, 0, C2, HW, 0, 0, C3, (long)C2 * HW, 0, (long)C3 * HW);
    tgemm_kernel<false,false,false,true,false,false><<<gridProj, 256, GSMEM>>>(
        Wc + WOFF_V, F_cam, nullptr, nullptr, nullptr, Vtb, nullptr, nullptr,
        C3, HW, C2, 0, C2, HW, 0, 0, C3, (long)C2 * HW, 0, (long)C3 * HW);

    attn_kernel<<<dim3(WW2 / 8, HH / 8, BB * HEADS), 128>>>(Qtb, Ktb, Vtb, AOb);

    // T1 = Wo*AO + Wr*F_lidar  (fused dual-K)
    tgemm_kernel<false,false,false,false,true,false><<<gridProj, 256, GSMEM>>>(
        Wc + WOFF_O, AOb, Wc + WOFF_R, F_lidar, T1b, nullptr, nullptr, nullptr,
        C3, HW, C3, C1, C3, HW, C1, HW, HW,
        (long)C3 * HW, (long)C1 * HW, (long)C3 * HW);

    ln1_kernel<<<NPIX / 32, 256>>>(T1b, Xb, g1, b1);

    // Y = relu(X*W1 + bf1), rna-rounded (sole consumer: FFN2 A-operand)
    tgemm_kernel<true,true,false,false,false,true><<<dim3(CF / BN, NPIX / BM, 1), 256, GSMEM>>>(
        Xb, Wc + WOFF_1, nullptr, nullptr, Yb, nullptr, bf1, nullptr,
        NPIX, CF, C3, 0, C3, CF, 0, 0, CF, 0, 0, 0);

    // Z = Y*W2 + bf2 + X
    tgemm_kernel<true,false,true,false,false,false><<<dim3(C3 / BN, NPIX / BM, 1), 256, GSMEM>>>(
        Yb, Wc + WOFF_2, nullptr, nullptr, Zb, nullptr, bf2, Xb,
        NPIX, C3, CF, 0, CF, C3, 0, 0, C3, 0, 0, 0);

    ln2_kernel<<<NPIX / 32, 256>>>(Zb, out, g2, b2);
}

// round 10
// speedup vs baseline: 5.0353x; 1.3821x over previous
#include <cuda_runtime.h>
#include <cuda_bf16.h>
#include <math.h>
#include <stdint.h>

// ---------------- problem constants ----------------
#define BB    2
#define C1    64
#define C2    256
#define C3    256
#define HH    200
#define WW2   200
#define HW    40000
#define NPIX  80000
#define HEADS 8
#define HD    32
#define WS    7
#define PADW  3
#define CF    1024
#define SCALE 0.17677669529663689f
#define LNEPS 1e-5f

// ---------------- scratch (device globals; no runtime allocation) ----------------
__device__ __nv_bfloat16 g_Qt[(long)NPIX*C3];
__device__ __nv_bfloat16 g_Kt[(long)NPIX*C3];
__device__ __nv_bfloat16 g_Vt[(long)NPIX*C3];
__device__ float g_AO[(long)BB*C3*HW];
__device__ float g_T1[(long)BB*C3*HW];
__device__ float g_X [(long)NPIX*C3];
__device__ __nv_bfloat16 g_Xb[(long)NPIX*C3];
__device__ __nv_bfloat16 g_Yb[(long)NPIX*CF];
__device__ float g_Z [(long)NPIX*C3];

// bf16 copies of GEMM inputs
#define FLN ((long)BB*C1*HW)      // 5,120,000
#define FCN ((long)BB*C2*HW)      // 20,480,000
__device__ __nv_bfloat16 g_Flb[FLN];
__device__ __nv_bfloat16 g_Fcb[FCN];

// bf16 weights, packed: Wq|Wk|Wv|W1|W2
#define HOFF_Q 0
#define HOFF_K 16384
#define HOFF_V 81920
#define HOFF_1 147456
#define HOFF_2 409600
#define HTOT   671744
__device__ __nv_bfloat16 g_Wh[HTOT];

// tf32 weights for the main-path GEMM: Wo|Wr
#define COFF_O 0
#define COFF_R 65536
#define CTOT   81920
__device__ float g_Wc[CTOT];

// ---------------- helpers ----------------
__device__ __forceinline__ float to_tf32(float x) {
    uint32_t u;
    asm("cvt.rna.tf32.f32 %0, %1;" : "=r"(u) : "f"(x));
    return __uint_as_float(u);
}

__device__ __forceinline__ void mma_tf32(float* c, const uint32_t* a, const uint32_t* b) {
    asm volatile(
        "mma.sync.aligned.m16n8k8.row.col.f32.tf32.tf32.f32 "
        "{%0,%1,%2,%3},{%4,%5,%6,%7},{%8,%9},{%0,%1,%2,%3};"
        : "+f"(c[0]), "+f"(c[1]), "+f"(c[2]), "+f"(c[3])
        : "r"(a[0]), "r"(a[1]), "r"(a[2]), "r"(a[3]), "r"(b[0]), "r"(b[1]));
}

__device__ __forceinline__ void mma_bf16(float* c, const uint32_t* a, const uint32_t* b) {
    asm volatile(
        "mma.sync.aligned.m16n8k16.row.col.f32.bf16.bf16.f32 "
        "{%0,%1,%2,%3},{%4,%5,%6,%7},{%8,%9},{%0,%1,%2,%3};"
        : "+f"(c[0]), "+f"(c[1]), "+f"(c[2]), "+f"(c[3])
        : "r"(a[0]), "r"(a[1]), "r"(a[2]), "r"(a[3]), "r"(b[0]), "r"(b[1]));
}

__device__ __forceinline__ void ldsm4(uint32_t& r0, uint32_t& r1, uint32_t& r2, uint32_t& r3,
                                      uint32_t addr) {
    asm volatile("ldmatrix.sync.aligned.m8n8.x4.shared.b16 {%0,%1,%2,%3},[%4];"
                 : "=r"(r0), "=r"(r1), "=r"(r2), "=r"(r3) : "r"(addr));
}

__device__ __forceinline__ void ldsm4t(uint32_t& r0, uint32_t& r1, uint32_t& r2, uint32_t& r3,
                                       uint32_t addr) {
    asm volatile("ldmatrix.sync.aligned.m8n8.x4.trans.shared.b16 {%0,%1,%2,%3},[%4];"
                 : "=r"(r0), "=r"(r1), "=r"(r2), "=r"(r3) : "r"(addr));
}

__device__ __forceinline__ uint32_t saddr(const void* p) {
    return (uint32_t)__cvta_generic_to_shared(p);
}

__device__ __forceinline__ uint32_t packbf2(float a, float b) {
    __nv_bfloat162 t = __floats2bfloat162_rn(a, b);
    return *reinterpret_cast<uint32_t*>(&t);
}

__device__ __forceinline__ void cpa16(uint32_t dst, const void* src, int sz) {
    asm volatile("cp.async.cg.shared.global [%0], [%1], 16, %2;\n"
                 :: "r"(dst), "l"(src), "r"(sz));
}
__device__ __forceinline__ void cpa_commit() {
    asm volatile("cp.async.commit_group;\n" ::: "memory");
}
template<int N_>
__device__ __forceinline__ void cpa_wait() {
    asm volatile("cp.async.wait_group %0;\n" :: "n"(N_) : "memory");
}

// ---------------- pre-conversion kernels ----------------
__global__ void wconv_h_kernel(const float* wq, const float* wk, const float* wv,
                               const float* w1, const float* w2, __nv_bfloat16* dst)
{
    long i = ((long)blockIdx.x * 256 + threadIdx.x) * 4;
    if (i >= HTOT) return;
    const float* src; long off;
    if      (i < HOFF_K) { src = wq; off = HOFF_Q; }
    else if (i < HOFF_V) { src = wk; off = HOFF_K; }
    else if (i < HOFF_1) { src = wv; off = HOFF_V; }
    else if (i < HOFF_2) { src = w1; off = HOFF_1; }
    else                 { src = w2; off = HOFF_2; }
    float4 v = *reinterpret_cast<const float4*>(src + (i - off));
    __nv_bfloat162 a = __floats2bfloat162_rn(v.x, v.y);
    __nv_bfloat162 b = __floats2bfloat162_rn(v.z, v.w);
    *reinterpret_cast<__nv_bfloat162*>(dst + i)     = a;
    *reinterpret_cast<__nv_bfloat162*>(dst + i + 2) = b;
}

__global__ void wconv_t_kernel(const float* wo, const float* wr, float* dst)
{
    int i = (blockIdx.x * 256 + threadIdx.x) * 4;
    if (i >= CTOT) return;
    const float* src = (i < COFF_R) ? wo : wr;
    int off = (i < COFF_R) ? COFF_O : COFF_R;
    float4 v = *reinterpret_cast<const float4*>(src + (i - off));
    v.x = to_tf32(v.x); v.y = to_tf32(v.y); v.z = to_tf32(v.z); v.w = to_tf32(v.w);
    *reinterpret_cast<float4*>(dst + i) = v;
}

__global__ void fconv_kernel(const float* fl, const float* fc,
                             __nv_bfloat16* flb, __nv_bfloat16* fcb)
{
    long i = ((long)blockIdx.x * 256 + threadIdx.x) * 4;
    const float* src; __nv_bfloat16* dst; long j;
    if (i < FLN)            { src = fl; dst = flb; j = i; }
    else if (i < FLN + FCN) { src = fc; dst = fcb; j = i - FLN; }
    else return;
    float4 v = *reinterpret_cast<const float4*>(src + j);
    *reinterpret_cast<__nv_bfloat162*>(dst + j)     = __floats2bfloat162_rn(v.x, v.y);
    *reinterpret_cast<__nv_bfloat162*>(dst + j + 2) = __floats2bfloat162_rn(v.z, v.w);
}

// ---------------- bf16 GEMM: cp.async 3-stage + ldmatrix + m16n8k16 ----------------
// C[M,N] = A[M,K]bf16(row, lda) * B[K,N]bf16(row, ldb)
// BF16T: bf16 transposed store Cbf[c*ldc+r]; OUTBF: bf16 row-major out.
// Requires M%128==0, K%32==0, N%8==0.
#define HBK  32
#define HKR  40     // As row stride (bf16): 80 B, LDSM conflict-free
#define HBR  136    // Bs row stride (bf16): 272 B, LDSM conflict-free
#define HST  3
#define HSMEM (HST * (128 * HKR + HBK * HBR) * 2)   // 56832 B

template<bool BIAS, bool RELU, bool RESID, bool BF16T, bool OUTBF>
__global__ __launch_bounds__(256, 2)
void hgemm_kernel(const __nv_bfloat16* __restrict__ A, const __nv_bfloat16* __restrict__ B,
                  float* __restrict__ C, __nv_bfloat16* __restrict__ Cbf,
                  const float* __restrict__ bias, const float* __restrict__ Res,
                  int M, int N, int K, int lda, int ldb, int ldc,
                  long strideB, long strideC)
{
    extern __shared__ __nv_bfloat16 hsm[];
    __nv_bfloat16* AsBase = hsm;                        // [HST][128][HKR]
    __nv_bfloat16* BsBase = hsm + HST * 128 * HKR;      // [HST][HBK][HBR]

    B += (long)blockIdx.z * strideB;
    if (BF16T || OUTBF) Cbf += (long)blockIdx.z * strideC;
    else                C   += (long)blockIdx.z * strideC;

    const int tid  = threadIdx.x;
    const int lane = tid & 31;
    const int warp = tid >> 5;
    const int warpM = (warp >> 2) * 64;
    const int warpN = (warp & 3) * 32;
    const int lr = lane >> 2;
    const int lc = lane & 3;

    const int rowBase = blockIdx.y * 128;
    const int colBase = blockIdx.x * 128;

    // A loader: rows aR, aR+64; 4 chunks of 16B (8 bf16) per row
    const int aR = tid >> 2;              // 0..63
    const int aS = (tid & 3) * 8;         // bf16 offset of 16B chunk
    // B loader: rows bK, bK+16; 16 chunks per row
    const int bK = tid >> 4;              // 0..15
    const int bS = (tid & 15) * 8;
    const int bOk = (colBase + bS + 8 <= N) ? 16 : 0;

    float acc[4][4][4];
    #pragma unroll
    for (int i = 0; i < 4; i++)
        #pragma unroll
        for (int j = 0; j < 4; j++)
            #pragma unroll
            for (int e = 0; e < 4; e++) acc[i][j][e] = 0.f;

    const int numT = K / HBK;

    // prologue
    #pragma unroll
    for (int t = 0; t < HST - 1; t++) {
        if (t < numT) {
            const int k0 = t * HBK;
            __nv_bfloat16* Asp = AsBase + t * 128 * HKR;
            __nv_bfloat16* Bsp = BsBase + t * HBK * HBR;
            #pragma unroll
            for (int u = 0; u < 2; u++)
                cpa16(saddr(Asp + (aR + 64 * u) * HKR + aS),
                      A + (long)(rowBase + aR + 64 * u) * lda + k0 + aS, 16);
            #pragma unroll
            for (int u = 0; u < 2; u++)
                cpa16(saddr(Bsp + (bK + 16 * u) * HBR + bS),
                      B + (long)(k0 + bK + 16 * u) * ldb + colBase + bS, bOk);
        }
        cpa_commit();
    }

    for (int t = 0; t < numT; t++) {
        cpa_wait<HST - 2>();
        __syncthreads();

        {
            const int tn = t + HST - 1;
            if (tn < numT) {
                const int k0 = tn * HBK;
                const int st = tn % HST;
                __nv_bfloat16* Asp = AsBase + st * 128 * HKR;
                __nv_bfloat16* Bsp = BsBase + st * HBK * HBR;
                #pragma unroll
                for (int u = 0; u < 2; u++)
                    cpa16(saddr(Asp + (aR + 64 * u) * HKR + aS),
                          A + (long)(rowBase + aR + 64 * u) * lda + k0 + aS, 16);
                #pragma unroll
                for (int u = 0; u < 2; u++)
                    cpa16(saddr(Bsp + (bK + 16 * u) * HBR + bS),
                          B + (long)(k0 + bK + 16 * u) * ldb + colBase + bS, bOk);
            }
            cpa_commit();
        }

        const int cur = t % HST;
        const __nv_bfloat16* Asc = AsBase + cur * 128 * HKR;
        const __nv_bfloat16* Bsc = BsBase + cur * HBK * HBR;

        #pragma unroll
        for (int kk = 0; kk < HBK; kk += 16) {
            uint32_t af[4][4];
            #pragma unroll
            for (int ti = 0; ti < 4; ti++)
                ldsm4(af[ti][0], af[ti][1], af[ti][2], af[ti][3],
                      saddr(Asc + (warpM + 16 * ti + (lane & 15)) * HKR
                                + kk + (lane >> 4) * 8));
            uint32_t bfr[4][2];
            #pragma unroll
            for (int g = 0; g < 2; g++) {
                uint32_t r0, r1, r2, r3;
                ldsm4t(r0, r1, r2, r3,
                       saddr(Bsc + (kk + (lane & 7) + ((lane >> 3) & 1) * 8) * HBR
                                 + warpN + g * 16 + (lane >> 4) * 8));
                bfr[2 * g][0] = r0; bfr[2 * g][1] = r1;
                bfr[2 * g + 1][0] = r2; bfr[2 * g + 1][1] = r3;
            }
            #pragma unroll
            for (int ti = 0; ti < 4; ti++)
                #pragma unroll
                for (int tj = 0; tj < 4; tj++)
                    mma_bf16(acc[ti][tj], af[ti], bfr[tj]);
        }
    }

    // epilogue
    #pragma unroll
    for (int ti = 0; ti < 4; ti++) {
        #pragma unroll
        for (int h = 0; h < 2; h++) {
            int r = rowBase + warpM + 16 * ti + lr + 8 * h;
            #pragma unroll
            for (int tj = 0; tj < 4; tj++) {
                int c = colBase + warpN + 8 * tj + 2 * lc;
                if (c >= N) continue;
                float v0 = acc[ti][tj][2 * h + 0];
                float v1 = acc[ti][tj][2 * h + 1];
                if (BIAS)  { v0 += bias[c]; v1 += bias[c + 1]; }
                if (RELU)  { v0 = fmaxf(v0, 0.f); v1 = fmaxf(v1, 0.f); }
                if (BF16T) {
                    Cbf[(long)c * ldc + r]       = __float2bfloat16(v0);
                    Cbf[(long)(c + 1) * ldc + r] = __float2bfloat16(v1);
                } else if (OUTBF) {
                    *reinterpret_cast<__nv_bfloat162*>(&Cbf[(long)r * ldc + c]) =
                        __floats2bfloat162_rn(v0, v1);
                } else {
                    long idx = (long)r * ldc + c;
                    if (RESID) { float2 rr = *reinterpret_cast<const float2*>(&Res[idx]);
                                 v0 += rr.x; v1 += rr.y; }
                    *reinterpret_cast<float2*>(&C[idx]) = make_float2(v0, v1);
                }
            }
        }
    }
}

// ---------------- tf32 GEMM (dual-K fused, main path) ----------------
#define BM 128
#define BN 128
#define BKT 16
#define NSTAGE 3
#define GSMEM ((NSTAGE*BM*(BKT+4) + NSTAGE*BKT*(BN+8)) * 4)

__global__ __launch_bounds__(256, 2)
void tgemm_dual_kernel(const float* __restrict__ A, const float* __restrict__ B,
                       const float* __restrict__ A2, const float* __restrict__ B2,
                       float* __restrict__ C,
                       int M, int N, int K, int K2,
                       int lda, int ldb, int lda2, int ldb2, int ldc,
                       long strideB, long strideB2, long strideC)
{
    extern __shared__ float dsm[];
    typedef float (*AsT)[BM][BKT + 4];
    typedef float (*BsT)[BKT][BN + 8];
    AsT As = reinterpret_cast<AsT>(dsm);
    BsT Bs = reinterpret_cast<BsT>(dsm + NSTAGE * BM * (BKT + 4));

    B  += (long)blockIdx.z * strideB;
    B2 += (long)blockIdx.z * strideB2;
    C  += (long)blockIdx.z * strideC;

    const int tid  = threadIdx.x;
    const int lane = tid & 31;
    const int warp = tid >> 5;
    const int warpM = (warp >> 2) * 64;
    const int warpN = (warp & 3) * 32;
    const int lr = lane >> 2;
    const int lc = lane & 3;

    const int rowBase = blockIdx.y * BM;
    const int colBase = blockIdx.x * BN;

    const int aR  = tid >> 2;
    const int aK4 = (tid & 3) * 4;
    const int bK  = tid >> 5;
    const int bC4 = (tid & 31) * 4;
    const int bOk = (colBase + bC4 < N) ? 16 : 0;

    float acc[4][4][4];
    #pragma unroll
    for (int i = 0; i < 4; i++)
        #pragma unroll
        for (int j = 0; j < 4; j++)
            #pragma unroll
            for (int e = 0; e < 4; e++) acc[i][j][e] = 0.f;

    #pragma unroll
    for (int ph = 0; ph < 2; ph++) {
        const float* Ap  = ph ? A2  : A;
        const float* Bp  = ph ? B2  : B;
        const int Kp     = ph ? K2  : K;
        const int ldap   = ph ? lda2 : lda;
        const int ldbp   = ph ? ldb2 : ldb;
        const int numT   = Kp / BKT;

        if (ph) __syncthreads();

        #pragma unroll
        for (int t = 0; t < NSTAGE - 1; t++) {
            if (t < numT) {
                const int k0 = t * BKT;
                #pragma unroll
                for (int u = 0; u < 2; u++)
                    cpa16(saddr(&As[t][aR + 64 * u][aK4]),
                          &Ap[(long)(rowBase + aR + 64 * u) * ldap + k0 + aK4], 16);
                #pragma unroll
                for (int u = 0; u < 2; u++)
                    cpa16(saddr(&Bs[t][bK + 8 * u][bC4]),
                          &Bp[(long)(k0 + bK + 8 * u) * ldbp + colBase + bC4], bOk);
            }
            cpa_commit();
        }

        for (int t = 0; t < numT; t++) {
            cpa_wait<NSTAGE - 2>();
            __syncthreads();
            {
                const int tn = t + NSTAGE - 1;
                if (tn < numT) {
                    const int k0 = tn * BKT;
                    const int st = tn % NSTAGE;
                    #pragma unroll
                    for (int u = 0; u < 2; u++)
                        cpa16(saddr(&As[st][aR + 64 * u][aK4]),
                              &Ap[(long)(rowBase + aR + 64 * u) * ldap + k0 + aK4], 16);
                    #pragma unroll
                    for (int u = 0; u < 2; u++)
                        cpa16(saddr(&Bs[st][bK + 8 * u][bC4]),
                              &Bp[(long)(k0 + bK + 8 * u) * ldbp + colBase + bC4], bOk);
                }
                cpa_commit();
            }

            const int cur = t % NSTAGE;
            #pragma unroll
            for (int kk = 0; kk < BKT; kk += 8) {
                uint32_t af[4][4], bf[4][2];
                #pragma unroll
                for (int ti = 0; ti < 4; ti++) {
                    int m = warpM + 16 * ti;
                    af[ti][0] = __float_as_uint(As[cur][m + lr    ][kk + lc    ]);
                    af[ti][1] = __float_as_uint(As[cur][m + lr + 8][kk + lc    ]);
                    af[ti][2] = __float_as_uint(As[cur][m + lr    ][kk + lc + 4]);
                    af[ti][3] = __float_as_uint(As[cur][m + lr + 8][kk + lc + 4]);
                }
                #pragma unroll
                for (int tj = 0; tj < 4; tj++) {
                    int n = warpN + 8 * tj;
                    bf[tj][0] = __float_as_uint(Bs[cur][kk + lc    ][n + lr]);
                    bf[tj][1] = __float_as_uint(Bs[cur][kk + lc + 4][n + lr]);
                }
                #pragma unroll
                for (int ti = 0; ti < 4; ti++)
                    #pragma unroll
                    for (int tj = 0; tj < 4; tj++)
                        mma_tf32(acc[ti][tj], af[ti], bf[tj]);
            }
        }
    }

    #pragma unroll
    for (int ti = 0; ti < 4; ti++) {
        #pragma unroll
        for (int h = 0; h < 2; h++) {
            int r = rowBase + warpM + 16 * ti + lr + 8 * h;
            #pragma unroll
            for (int tj = 0; tj < 4; tj++) {
                int c = colBase + warpN + 8 * tj + 2 * lc;
                if (c >= N) continue;
                long idx = (long)r * ldc + c;
                *reinterpret_cast<float2*>(&C[idx]) =
                    make_float2(acc[ti][tj][2 * h], acc[ti][tj][2 * h + 1]);
            }
        }
    }
}

// ---------------- local-window attention: tensor-core flash style ----------------
#define NKP 208
#define KR  40

__global__ __launch_bounds__(128, 5)
void attn_kernel(const __nv_bfloat16* __restrict__ Qt, const __nv_bfloat16* __restrict__ Kt,
                 const __nv_bfloat16* __restrict__ Vt, float* __restrict__ Og0)
{
    __shared__ __align__(16) __nv_bfloat16 sK[NKP * KR];
    __shared__ __align__(16) __nv_bfloat16 sV[NKP * KR];
    __shared__ __align__(16) __nv_bfloat16 sQ[64 * KR];

    const int tid  = threadIdx.x;
    const int lane = tid & 31;
    const int warp = tid >> 5;

    const int b  = blockIdx.z >> 3;
    const int hd = blockIdx.z & 7;
    const int h0 = blockIdx.y * 8, w0 = blockIdx.x * 8;

    const long tBase = (long)b * HW * C3 + hd * HD;
    const __nv_bfloat16* Kb = Kt + tBase;
    const __nv_bfloat16* Vb = Vt + tBase;
    const __nv_bfloat16* Qb = Qt + tBase;

    for (int i = tid; i < 196 * 4; i += 128) {
        const int p = i >> 2, seg = i & 3;
        int ph = h0 - PADW + p / 14;
        int pw = w0 - PADW + p % 14;
        ph = ph < 0 ? 0 : (ph > HH - 1 ? HH - 1 : ph);
        pw = pw < 0 ? 0 : (pw > WW2 - 1 ? WW2 - 1 : pw);
        const long src = (long)(ph * WW2 + pw) * C3 + seg * 8;
        *reinterpret_cast<uint4*>(&sK[p * KR + seg * 8]) =
            *reinterpret_cast<const uint4*>(Kb + src);
        *reinterpret_cast<uint4*>(&sV[p * KR + seg * 8]) =
            *reinterpret_cast<const uint4*>(Vb + src);
    }
    for (int i = tid; i < 12 * 4; i += 128) {
        const int p = 196 + (i >> 2), seg = i & 3;
        uint4 z = make_uint4(0u, 0u, 0u, 0u);
        *reinterpret_cast<uint4*>(&sK[p * KR + seg * 8]) = z;
        *reinterpret_cast<uint4*>(&sV[p * KR + seg * 8]) = z;
    }
    for (int i = tid; i < 64 * 4; i += 128) {
        const int p = i >> 2, seg = i & 3;
        const long src = (long)((h0 + (p >> 3)) * WW2 + (w0 + (p & 7))) * C3 + seg * 8;
        *reinterpret_cast<uint4*>(&sQ[p * KR + seg * 8]) =
            *reinterpret_cast<const uint4*>(Qb + src);
    }
    __syncthreads();

    const int lr = lane >> 2, lc = lane & 3;
    const int ty0 = 2 * warp;
    const int tx  = lr;

    uint32_t aq0[4], aq1[4];
    {
        int qrow = 16 * warp + (lane & 15);
        int qcol = (lane >> 4) * 8;
        ldsm4(aq0[0], aq0[1], aq0[2], aq0[3], saddr(&sQ[qrow * KR + qcol]));
        ldsm4(aq1[0], aq1[1], aq1[2], aq1[3], saddr(&sQ[qrow * KR + 16 + qcol]));
    }

    float m20 = -60.f, m21 = -60.f;
    float l0 = 0.f, l1 = 0.f;
    float acco[4][4];
    #pragma unroll
    for (int i = 0; i < 4; i++)
        #pragma unroll
        for (int j = 0; j < 4; j++) acco[i][j] = 0.f;

    const float LSC = SCALE * 1.4426950408889634f;
    const int c0 = (28 * warp) >> 4;
    const int c1 = (28 * warp + 111) >> 4;

    for (int c = c0; c <= c1; c++) {
        const int n0 = c * 16;

        float s0[4] = {0.f, 0.f, 0.f, 0.f};
        float s1[4] = {0.f, 0.f, 0.f, 0.f};
        {
            const int krow = n0 + (lane & 7) + ((lane >> 3) & 1) * 8;
            const int kcol = (lane >> 4) * 8;
            uint32_t r0, r1, r2, r3;
            ldsm4(r0, r1, r2, r3, saddr(&sK[krow * KR + kcol]));
            { uint32_t f[2] = {r0, r2}; mma_bf16(s0, aq0, f); }
            { uint32_t f[2] = {r1, r3}; mma_bf16(s1, aq0, f); }
            ldsm4(r0, r1, r2, r3, saddr(&sK[krow * KR + 16 + kcol]));
            { uint32_t f[2] = {r0, r2}; mma_bf16(s0, aq1, f); }
            { uint32_t f[2] = {r1, r3}; mma_bf16(s1, aq1, f); }
        }

        float pv0[4], pv1[4];
        float cm0 = -1e30f, cm1 = -1e30f;
        #pragma unroll
        for (int u = 0; u < 4; u++) {
            const int t = u >> 1, j = u & 1;
            const int col = n0 + 8 * t + 2 * lc + j;
            const int hy = (col * 2341) >> 15;
            const int hx = col - 14 * hy;
            const int dy = hy - ty0;
            const bool okx = (unsigned)(hx - tx) <= 6u;
            const float v0 = (t ? s1[j]     : s0[j])     * LSC;
            const float v1 = (t ? s1[j + 2] : s0[j + 2]) * LSC;
            const float e0 = (okx && (unsigned)dy       <= 6u) ? v0 : -1e30f;
            const float e1 = (okx && (unsigned)(dy - 1) <= 6u) ? v1 : -1e30f;
            pv0[u] = e0; pv1[u] = e1;
            cm0 = fmaxf(cm0, e0); cm1 = fmaxf(cm1, e1);
        }
        cm0 = fmaxf(cm0, __shfl_xor_sync(0xffffffffu, cm0, 1));
        cm0 = fmaxf(cm0, __shfl_xor_sync(0xffffffffu, cm0, 2));
        cm1 = fmaxf(cm1, __shfl_xor_sync(0xffffffffu, cm1, 1));
        cm1 = fmaxf(cm1, __shfl_xor_sync(0xffffffffu, cm1, 2));

        const float mn0 = fmaxf(m20, cm0), mn1 = fmaxf(m21, cm1);
        const float fs0 = exp2f(m20 - mn0), fs1 = exp2f(m21 - mn1);
        m20 = mn0; m21 = mn1;

        #pragma unroll
        for (int u = 0; u < 4; u++) {
            pv0[u] = exp2f(pv0[u] - mn0);
            pv1[u] = exp2f(pv1[u] - mn1);
        }
        l0 = l0 * fs0 + pv0[0] + pv0[1] + pv0[2] + pv0[3];
        l1 = l1 * fs1 + pv1[0] + pv1[1] + pv1[2] + pv1[3];

        #pragma unroll
        for (int vt = 0; vt < 4; vt++) {
            acco[vt][0] *= fs0; acco[vt][1] *= fs0;
            acco[vt][2] *= fs1; acco[vt][3] *= fs1;
        }

        uint32_t pa[4];
        pa[0] = packbf2(pv0[0], pv0[1]);
        pa[1] = packbf2(pv1[0], pv1[1]);
        pa[2] = packbf2(pv0[2], pv0[3]);
        pa[3] = packbf2(pv1[2], pv1[3]);

        {
            const int vrow = n0 + (lane & 7) + ((lane >> 3) & 1) * 8;
            const int vcol = (lane >> 4) * 8;
            uint32_t r0, r1, r2, r3;
            ldsm4t(r0, r1, r2, r3, saddr(&sV[vrow * KR + vcol]));
            { uint32_t f[2] = {r0, r1}; mma_bf16(acco[0], pa, f); }
            { uint32_t f[2] = {r2, r3}; mma_bf16(acco[1], pa, f); }
            ldsm4t(r0, r1, r2, r3, saddr(&sV[vrow * KR + 16 + vcol]));
            { uint32_t f[2] = {r0, r1}; mma_bf16(acco[2], pa, f); }
            { uint32_t f[2] = {r2, r3}; mma_bf16(acco[3], pa, f); }
        }
    }

    l0 += __shfl_xor_sync(0xffffffffu, l0, 1);
    l0 += __shfl_xor_sync(0xffffffffu, l0, 2);
    l1 += __shfl_xor_sync(0xffffffffu, l1, 1);
    l1 += __shfl_xor_sync(0xffffffffu, l1, 2);
    const float inv0 = 1.f / l0, inv1 = 1.f / l1;

    const int pr = 16 * warp + lr;
    const long po0 = (long)(h0 + (pr >> 3)) * WW2 + (w0 + lr);
    const long po1 = po0 + WW2;
    float* Ob = Og0 + ((long)b * C3 + hd * HD) * HW;
    #pragma unroll
    for (int vt = 0; vt < 4; vt++) {
        #pragma unroll
        for (int j = 0; j < 2; j++) {
            const int ch = 8 * vt + 2 * lc + j;
            Ob[(long)ch * HW + po0] = to_tf32(acco[vt][j]     * inv0);
            Ob[(long)ch * HW + po1] = to_tf32(acco[vt][2 + j] * inv1);
        }
    }
}

// ---------------- LayerNorm 1: planar -> row-major fp32 X + bf16 Xb ----------------
__global__ __launch_bounds__(256)
void ln1_kernel(const float* __restrict__ T1, float* __restrict__ X,
                __nv_bfloat16* __restrict__ Xb,
                const float* __restrict__ g, const float* __restrict__ bta)
{
    __shared__ float s[C3][33];
    const int tid = threadIdx.x;
    const long base = (long)blockIdx.x * 32;
    const int b  = (int)(base / HW);
    const int n0 = (int)(base % HW);
    const float* Tb = T1 + (long)b * C3 * HW + n0;

    for (int i = tid; i < C3 * 32; i += 256) {
        int c = i >> 5, l = i & 31;
        s[c][l] = Tb[(long)c * HW + l];
    }
    __syncthreads();

    const int warp = tid >> 5, lane = tid & 31;
    for (int p = warp * 4; p < warp * 4 + 4; p++) {
        float sum = 0.f, sq = 0.f;
        #pragma unroll
        for (int k = 0; k < 8; k++) {
            float v = s[lane + 32 * k][p];
            sum += v; sq += v * v;
        }
        #pragma unroll
        for (int o = 16; o > 0; o >>= 1) {
            sum += __shfl_xor_sync(0xffffffffu, sum, o);
            sq  += __shfl_xor_sync(0xffffffffu, sq,  o);
        }
        float mu   = sum * (1.f / C3);
        float var  = sq * (1.f / C3) - mu * mu;
        float rstd = rsqrtf(var + LNEPS);
        float* Xr = X + (base + p) * (long)C3;
        __nv_bfloat16* Xbr = Xb + (base + p) * (long)C3;
        #pragma unroll
        for (int k = 0; k < 8; k++) {
            int c = lane + 32 * k;
            float v = (s[c][p] - mu) * rstd * g[c] + bta[c];
            Xr[c]  = v;
            Xbr[c] = __float2bfloat16(v);
        }
    }
}

// ---------------- LayerNorm 2: row-major (N,C3) -> planar (B,C3,HW) ----------------
__global__ __launch_bounds__(256)
void ln2_kernel(const float* __restrict__ Z, float* __restrict__ Out,
                const float* __restrict__ g, const float* __restrict__ bta)
{
    __shared__ float s[C3][33];
    const int tid = threadIdx.x;
    const long base = (long)blockIdx.x * 32;
    const int b  = (int)(base / HW);
    const int n0 = (int)(base % HW);

    for (int i = tid; i < 32 * C3; i += 256) {
        int p = i >> 8, c = i & 255;
        s[c][p] = Z[(base + p) * (long)C3 + c];
    }
    __syncthreads();

    const int warp = tid >> 5, lane = tid & 31;
    for (int p = warp * 4; p < warp * 4 + 4; p++) {
        float sum = 0.f, sq = 0.f;
        #pragma unroll
        for (int k = 0; k < 8; k++) {
            float v = s[lane + 32 * k][p];
            sum += v; sq += v * v;
        }
        #pragma unroll
        for (int o = 16; o > 0; o >>= 1) {
            sum += __shfl_xor_sync(0xffffffffu, sum, o);
            sq  += __shfl_xor_sync(0xffffffffu, sq,  o);
        }
        float mu   = sum * (1.f / C3);
        float var  = sq * (1.f / C3) - mu * mu;
        float rstd = rsqrtf(var + LNEPS);
        #pragma unroll
        for (int k = 0; k < 8; k++) {
            int c = lane + 32 * k;
            s[c][p] = (s[c][p] - mu) * rstd * g[c] + bta[c];
        }
    }
    __syncthreads();

    float* Ob = Out + (long)b * C3 * HW + n0;
    for (int i = tid; i < C3 * 32; i += 256) {
        int c = i >> 5, l = i & 31;
        Ob[(long)c * HW + l] = s[c][l];
    }
}

// ---------------- launch ----------------
extern "C" void kernel_launch(void* const* d_in, const int* in_sizes, int n_in,
                              void* d_out, int out_size)
{
    const float* F_lidar = (const float*)d_in[0];
    const float* F_cam   = (const float*)d_in[1];
    const float* Wq  = (const float*)d_in[2];
    const float* Wk  = (const float*)d_in[3];
    const float* Wv  = (const float*)d_in[4];
    const float* Wo  = (const float*)d_in[5];
    const float* Wr  = (const float*)d_in[6];
    const float* g1  = (const float*)d_in[7];
    const float* b1  = (const float*)d_in[8];
    const float* g2  = (const float*)d_in[9];
    const float* b2  = (const float*)d_in[10];
    const float* W1  = (const float*)d_in[11];
    const float* bf1 = (const float*)d_in[12];
    const float* W2  = (const float*)d_in[13];
    const float* bf2 = (const float*)d_in[14];
    float* out = (float*)d_out;

    __nv_bfloat16 *Qtb, *Ktb, *Vtb, *Xbb, *Ybb, *Flb, *Fcb, *Wh;
    float *AOb, *T1b, *Xb, *Zb, *Wc;
    cudaGetSymbolAddress((void**)&Qtb, g_Qt);
    cudaGetSymbolAddress((void**)&Ktb, g_Kt);
    cudaGetSymbolAddress((void**)&Vtb, g_Vt);
    cudaGetSymbolAddress((void**)&AOb, g_AO);
    cudaGetSymbolAddress((void**)&T1b, g_T1);
    cudaGetSymbolAddress((void**)&Xb,  g_X);
    cudaGetSymbolAddress((void**)&Xbb, g_Xb);
    cudaGetSymbolAddress((void**)&Ybb, g_Yb);
    cudaGetSymbolAddress((void**)&Zb,  g_Z);
    cudaGetSymbolAddress((void**)&Flb, g_Flb);
    cudaGetSymbolAddress((void**)&Fcb, g_Fcb);
    cudaGetSymbolAddress((void**)&Wh,  g_Wh);
    cudaGetSymbolAddress((void**)&Wc,  g_Wc);

    cudaFuncSetAttribute((const void*)tgemm_dual_kernel,
                         cudaFuncAttributeMaxDynamicSharedMemorySize, GSMEM);
    cudaFuncSetAttribute((const void*)hgemm_kernel<false,false,false,true,false>,
                         cudaFuncAttributeMaxDynamicSharedMemorySize, HSMEM);
    cudaFuncSetAttribute((const void*)hgemm_kernel<true,true,false,false,true>,
                         cudaFuncAttributeMaxDynamicSharedMemorySize, HSMEM);
    cudaFuncSetAttribute((const void*)hgemm_kernel<true,false,true,false,false>,
                         cudaFuncAttributeMaxDynamicSharedMemorySize, HSMEM);

    // pre-conversions
    wconv_h_kernel<<<(HTOT / 4 + 255) / 256, 256>>>(Wq, Wk, Wv, W1, W2, Wh);
    wconv_t_kernel<<<(CTOT / 4 + 255) / 256, 256>>>(Wo, Wr, Wc);
    fconv_kernel<<<(int)((FLN + FCN) / 4 + 255) / 256, 256>>>(F_lidar, F_cam, Flb, Fcb);

    const dim3 gridProj((HW + 127) / 128, C3 / 128, BB);   // (313, 2, 2)

    // Q/K/V -> bf16 pixel-major (bf16 GEMM, transposed store)
    hgemm_kernel<false,false,false,true,false><<<gridProj, 256, HSMEM>>>(
        Wh + HOFF_Q, Flb, nullptr, Qtb, nullptr, nullptr,
        C3, HW, C1, C1, HW, C3, (long)C1 * HW, (long)C3 * HW);
    hgemm_kernel<false,false,false,true,false><<<gridProj, 256, HSMEM>>>(
        Wh + HOFF_K, Fcb, nullptr, Ktb, nullptr, nullptr,
        C3, HW, C2, C2, HW, C3, (long)C2 * HW, (long)C3 * HW);
    hgemm_kernel<false,false,false,true,false><<<gridProj, 256, HSMEM>>>(
        Wh + HOFF_V, Fcb, nullptr, Vtb, nullptr, nullptr,
        C3, HW, C2, C2, HW, C3, (long)C2 * HW, (long)C3 * HW);

    attn_kernel<<<dim3(WW2 / 8, HH / 8, BB * HEADS), 128>>>(Qtb, Ktb, Vtb, AOb);

    // T1 = Wo*AO + Wr*F_lidar  (tf32 dual, main path)
    tgemm_dual_kernel<<<gridProj, 256, GSMEM>>>(
        Wc + COFF_O, AOb, Wc + COFF_R, F_lidar, T1b,
        C3, HW, C3, C1, C3, HW, C1, HW, HW,
        (long)C3 * HW, (long)C1 * HW, (long)C3 * HW);

    ln1_kernel<<<NPIX / 32, 256>>>(T1b, Xb, Xbb, g1, b1);

    // Y = relu(Xb*W1 + bf1) -> bf16 row-major
    hgemm_kernel<true,true,false,false,true><<<dim3(CF / 128, NPIX / 128, 1), 256, HSMEM>>>(
        Xbb, Wh + HOFF_1, nullptr, Ybb, bf1, nullptr,
        NPIX, CF, C3, C3, CF, CF, 0, 0);

    // Z = Yb*W2 + bf2 + X (fp32 residual)
    hgemm_kernel<true,false,true,false,false><<<dim3(C3 / 128, NPIX / 128, 1), 256, HSMEM>>>(
        Ybb, Wh + HOFF_2, Zb, nullptr, bf2, Xb,
        NPIX, C3, CF, CF, C3, C3, 0, 0);

    ln2_kernel<<<NPIX / 32, 256>>>(Zb, out, g2, b2);
}